// round 12
// baseline (speedup 1.0000x reference)
#include <cuda_runtime.h>
#include <math.h>
#include <stdint.h>

// Problem constants
#define NB   4
#define LL   4096
#define SS   256
#define HH   256
#define FCn  8
#define SCn  32
#define MM   32      // NB*FCn
#define H2   512
#define KK   256     // inner dim of dense GEMMs

typedef unsigned long long u64;

// Scratch (device globals; no dynamic allocation allowed)
__device__ float    g_c1[NB * SS * H2];       // center1 @ W1^T + b1
__device__ uint32_t g_cpF[MM * 16384];        // cpN tf32 B-fragments, [bh0,bh1,bl0,bl1]
__device__ float    g_cv [MM * SS * SCn];     // c_value
__device__ float    g_x0p[NB * LL * HH];      // x0 @ W0^T + b0
__device__ float    g_disp[NB * LL * HH];     // dispatched

// ---------------------------------------------------------------------------
// PTX helpers
// ---------------------------------------------------------------------------
__device__ __forceinline__ u64 ffma2(u64 a, u64 b, u64 c) {
    u64 d;
    asm("fma.rn.f32x2 %0, %1, %2, %3;" : "=l"(d) : "l"(a), "l"(b), "l"(c));
    return d;
}
__device__ __forceinline__ u64 pack2(float x, float y) {
    u64 r;
    asm("mov.b64 %0, {%1, %2};" : "=l"(r) : "f"(x), "f"(y));
    return r;
}
__device__ __forceinline__ float2 unpack2(u64 v) {
    float2 f;
    asm("mov.b64 {%0, %1}, %2;" : "=f"(f.x), "=f"(f.y) : "l"(v));
    return f;
}
__device__ __forceinline__ uint32_t f2tf32(float x) {
    uint32_t r;
    asm("cvt.rna.tf32.f32 %0, %1;" : "=r"(r) : "f"(x));
    return r;
}
// m16n8k8 tf32 warp MMA, D += A*B (fp32 accum)
__device__ __forceinline__ void mma8(float4& d, const uint32_t* a, const uint32_t* b) {
    asm("mma.sync.aligned.m16n8k8.row.col.f32.tf32.tf32.f32 "
        "{%0,%1,%2,%3}, {%4,%5,%6,%7}, {%8,%9}, {%0,%1,%2,%3};"
        : "+f"(d.x), "+f"(d.y), "+f"(d.z), "+f"(d.w)
        : "r"(a[0]), "r"(a[1]), "r"(a[2]), "r"(a[3]), "r"(b[0]), "r"(b[1]));
}

// A-frag: [rowtile(16 rows)][ks][lane][4 regs]
__device__ __forceinline__ int afrag(int rowtile, int ks, int lane, int reg) {
    return ((rowtile * 4 + ks) * 32 + lane) * 4 + reg;
}
// B-frag (interleaved hi/lo): [ntile(8 cols)][ks][lane][bh0,bh1,bl0,bl1]
__device__ __forceinline__ int bfrag4(int ntile, int ks, int lane, int reg) {
    return ((ntile * 4 + ks) * 32 + lane) * 4 + reg;
}

// ---------------------------------------------------------------------------
// Tensor-core GEMM via mma.sync tf32 (row-major stride-36 smem, proven R9):
//   C[R][Hout] = A[R][256] @ B[Hout][256]^T + bias
// NPASS=1: plain tf32 — K4.  NPASS=3: hi/lo compensation (~fp32) — K2.
// Block tile 128x128, 8 warps: 4m x 2n; warp tile 32m x 64n.
// ---------------------------------------------------------------------------
template<int NPASS>
__global__ __launch_bounds__(256, 2) void gemm_mma(
    const float* __restrict__ A, const float* __restrict__ B,
    const float* __restrict__ bias, float* __restrict__ C, int Hout)
{
    extern __shared__ __align__(16) uint32_t msm[];
    uint32_t* Ah = msm;                                    // [128][36]
    uint32_t* Al = Ah + 4608;                              // NPASS==3 only
    uint32_t* Bh = (NPASS == 3) ? (Al + 4608) : (Ah + 4608);  // [128][36]
    uint32_t* Bl = Bh + 4608;                              // NPASS==3 only

    const int tid  = threadIdx.x;
    const int wid  = tid >> 5;
    const int lane = tid & 31;
    const int g  = lane >> 2;
    const int tg = lane & 3;
    const int mbase = (wid & 3) * 32;
    const int nbase = (wid >> 2) * 64;
    const int r0 = blockIdx.x * 128;
    const int h0 = blockIdx.y * 128;

    float4 acc[2][8];
    #pragma unroll
    for (int i = 0; i < 2; i++)
        #pragma unroll
        for (int j = 0; j < 8; j++) acc[i][j] = make_float4(0.f, 0.f, 0.f, 0.f);

    for (int c = 0; c < 8; c++) {
        __syncthreads();
        #pragma unroll
        for (int it = 0; it < 4; it++) {
            int idx = tid + it * 256;
            int row = idx >> 3, j = idx & 7;
            float4 v = *(const float4*)&A[(size_t)(r0 + row) * 256 + c * 32 + j * 4];
            uint32_t base = row * 36 + j * 4;
            float xs[4] = {v.x, v.y, v.z, v.w};
            #pragma unroll
            for (int t = 0; t < 4; t++) {
                uint32_t hi = f2tf32(xs[t]);
                Ah[base + t] = hi;
                if constexpr (NPASS == 3)
                    Al[base + t] = f2tf32(xs[t] - __uint_as_float(hi));
            }
        }
        #pragma unroll
        for (int it = 0; it < 4; it++) {
            int idx = tid + it * 256;
            int row = idx >> 3, j = idx & 7;
            float4 v = *(const float4*)&B[(size_t)(h0 + row) * 256 + c * 32 + j * 4];
            uint32_t base = row * 36 + j * 4;
            float xs[4] = {v.x, v.y, v.z, v.w};
            #pragma unroll
            for (int t = 0; t < 4; t++) {
                uint32_t hi = f2tf32(xs[t]);
                Bh[base + t] = hi;
                if constexpr (NPASS == 3)
                    Bl[base + t] = f2tf32(xs[t] - __uint_as_float(hi));
            }
        }
        __syncthreads();

        #pragma unroll
        for (int ks = 0; ks < 4; ks++) {
            const int k0 = ks * 8;
            uint32_t ah[2][4], al[2][4];
            #pragma unroll
            for (int i = 0; i < 2; i++) {
                uint32_t rb = (mbase + i * 16 + g) * 36 + k0 + tg;
                ah[i][0] = Ah[rb];
                ah[i][1] = Ah[rb + 8 * 36];
                ah[i][2] = Ah[rb + 4];
                ah[i][3] = Ah[rb + 8 * 36 + 4];
                if constexpr (NPASS == 3) {
                    al[i][0] = Al[rb];
                    al[i][1] = Al[rb + 8 * 36];
                    al[i][2] = Al[rb + 4];
                    al[i][3] = Al[rb + 8 * 36 + 4];
                }
            }
            #pragma unroll
            for (int j = 0; j < 8; j++) {
                uint32_t rb = (nbase + j * 8 + g) * 36 + k0 + tg;
                uint32_t bh[2] = {Bh[rb], Bh[rb + 4]};
                #pragma unroll
                for (int i = 0; i < 2; i++)
                    mma8(acc[i][j], ah[i], bh);
                if constexpr (NPASS == 3) {
                    uint32_t bl[2] = {Bl[rb], Bl[rb + 4]};
                    #pragma unroll
                    for (int i = 0; i < 2; i++) {
                        mma8(acc[i][j], ah[i], bl);
                        mma8(acc[i][j], al[i], bh);
                    }
                }
            }
        }
    }

    #pragma unroll
    for (int j = 0; j < 8; j++) {
        int col = h0 + nbase + j * 8 + 2 * tg;
        float2 bb = *(const float2*)&bias[col];
        #pragma unroll
        for (int i = 0; i < 2; i++) {
            int row = r0 + mbase + i * 16 + g;
            float2 o0 = make_float2(acc[i][j].x + bb.x, acc[i][j].y + bb.y);
            float2 o1 = make_float2(acc[i][j].z + bb.x, acc[i][j].w + bb.y);
            *(float2*)&C[(size_t)row * Hout + col] = o0;
            *(float2*)&C[(size_t)(row + 8) * Hout + col] = o1;
        }
    }
}

// ---------------------------------------------------------------------------
// Dense fp32 GEMM (K1 only)
// ---------------------------------------------------------------------------
template<int NT>
__global__ __launch_bounds__(256, 2) void gemm_nt(
    const float* __restrict__ A, const float* __restrict__ B,
    const float* __restrict__ bias, float* __restrict__ C, int Hout)
{
    constexpr int SN = NT / 16;
    __shared__ __align__(16) float as[32][132];
    __shared__ __align__(16) float bs[32][NT + 4];

    const int r0 = blockIdx.x * 128;
    const int h0 = blockIdx.y * NT;
    const int tid = threadIdx.x;
    const int tc = tid & 15;
    const int tr = tid >> 4;
    const int k4 = (tid & 7) * 4;
    const int rl = tid >> 3;

    u64 acc[4][SN];
    #pragma unroll
    for (int p = 0; p < 4; p++)
        #pragma unroll
        for (int j = 0; j < SN; j++) acc[p][j] = 0ull;

    for (int k0 = 0; k0 < KK; k0 += 32) {
        #pragma unroll
        for (int it = 0; it < 4; it++) {
            int row = rl + it * 32;
            float4 v = *(const float4*)&A[(size_t)(r0 + row) * KK + k0 + k4];
            as[k4 + 0][row] = v.x;
            as[k4 + 1][row] = v.y;
            as[k4 + 2][row] = v.z;
            as[k4 + 3][row] = v.w;
        }
        #pragma unroll
        for (int it = 0; it < NT / 32; it++) {
            int h = rl + it * 32;
            float4 v = *(const float4*)&B[(size_t)(h0 + h) * KK + k0 + k4];
            bs[k4 + 0][h] = v.x;
            bs[k4 + 1][h] = v.y;
            bs[k4 + 2][h] = v.z;
            bs[k4 + 3][h] = v.w;
        }
        __syncthreads();

        #pragma unroll 8
        for (int kk = 0; kk < 32; kk++) {
            ulonglong2 a01 = *(const ulonglong2*)&as[kk][tr * 8];
            ulonglong2 a23 = *(const ulonglong2*)&as[kk][tr * 8 + 4];
            u64 ap[4] = {a01.x, a01.y, a23.x, a23.y};
            #pragma unroll
            for (int jq = 0; jq < SN / 4; jq++) {
                float4 bv = *(const float4*)&bs[kk][tc * SN + jq * 4];
                u64 b0 = pack2(bv.x, bv.x);
                u64 b1 = pack2(bv.y, bv.y);
                u64 b2 = pack2(bv.z, bv.z);
                u64 b3 = pack2(bv.w, bv.w);
                #pragma unroll
                for (int p = 0; p < 4; p++) {
                    acc[p][jq * 4 + 0] = ffma2(ap[p], b0, acc[p][jq * 4 + 0]);
                    acc[p][jq * 4 + 1] = ffma2(ap[p], b1, acc[p][jq * 4 + 1]);
                    acc[p][jq * 4 + 2] = ffma2(ap[p], b2, acc[p][jq * 4 + 2]);
                    acc[p][jq * 4 + 3] = ffma2(ap[p], b3, acc[p][jq * 4 + 3]);
                }
            }
        }
        __syncthreads();
    }

    #pragma unroll
    for (int jq = 0; jq < SN / 4; jq++) {
        float4 bb = *(const float4*)&bias[h0 + tc * SN + jq * 4];
        #pragma unroll
        for (int p = 0; p < 4; p++) {
            float2 f0 = unpack2(acc[p][jq * 4 + 0]);
            float2 f1 = unpack2(acc[p][jq * 4 + 1]);
            float2 f2 = unpack2(acc[p][jq * 4 + 2]);
            float2 f3 = unpack2(acc[p][jq * 4 + 3]);
            int row0 = r0 + tr * 8 + 2 * p;
            float4 o0 = make_float4(f0.x + bb.x, f1.x + bb.y, f2.x + bb.z, f3.x + bb.w);
            float4 o1 = make_float4(f0.y + bb.x, f1.y + bb.y, f2.y + bb.z, f3.y + bb.w);
            *(float4*)&C[(size_t)row0 * Hout + h0 + tc * SN + jq * 4] = o0;
            *(float4*)&C[(size_t)(row0 + 1) * Hout + h0 + tc * SN + jq * 4] = o1;
        }
    }
}

// ---------------------------------------------------------------------------
// Split c1 -> c_point (l2-normalized, tf32 hi/lo interleaved B-fragments) / c_value.
// ---------------------------------------------------------------------------
__global__ __launch_bounds__(256) void center_norm_kernel()
{
    int w    = (blockIdx.x * blockDim.x + threadIdx.x) >> 5;
    int lane = threadIdx.x & 31;   // = k
    int m = w >> 8;
    int s = w & 255;
    int n = m >> 3, f = m & 7;

    const float* row = &g_c1[((size_t)(n * SS + s)) * H2 + f * 64];
    float p = row[lane];
    float v = row[32 + lane];

    float sq = p * p;
    #pragma unroll
    for (int off = 16; off; off >>= 1)
        sq += __shfl_xor_sync(0xffffffffu, sq, off);

    float d = fmaxf(sqrtf(sq), 1e-12f);
    float pn = p / d;
    uint32_t hi = f2tf32(pn);
    uint32_t lo = f2tf32(pn - __uint_as_float(hi));

    int base = bfrag4(s >> 3, lane >> 3, (s & 7) * 4 + (lane & 3), (lane >> 2) & 1);
    g_cpF[(size_t)m * 16384 + base]     = hi;   // bh reg 0/1
    g_cpF[(size_t)m * 16384 + base + 2] = lo;   // bl reg 2/3
    g_cv[((size_t)(m * SS + s)) * SCn + lane] = v;
}

// ---------------------------------------------------------------------------
// Fused sim (3xTF32 mma.sync) + tree-argmax + sigmoid + gather.
// B hi/lo interleaved -> one LDS.128 per (ks,j). grid (32 l-tiles, 32 m).
// ---------------------------------------------------------------------------
__global__ __launch_bounds__(256, 2) void sim_mma(
    const float* __restrict__ alpha_p, const float* __restrict__ beta_p)
{
    extern __shared__ __align__(16) uint32_t ssm[];
    uint32_t* AFh = ssm;                 // 8rt*4*32*4 = 4096
    uint32_t* AFl = AFh + 4096;
    uint32_t* BF  = AFl + 4096;          // 32nt*4*32*4 = 16384
    float*    smv = (float*)(BF + 16384);   // [128]
    int*      sms = (int*)(smv + 128);      // [128]

    const int m  = blockIdx.y;
    const int n  = m >> 3, f = m & 7;
    const int l0 = blockIdx.x * 128;
    const int tid  = threadIdx.x;
    const int wid  = tid >> 5;
    const int lane = tid & 31;
    const int g  = lane >> 2;
    const int tg = lane & 3;

    // A: load x0p rows, l2-normalize, tf32 hi/lo -> fragment layout
    #pragma unroll 4
    for (int i = 0; i < 16; i++) {
        int row = wid * 16 + i;
        float x = g_x0p[((size_t)(n * LL + l0 + row)) * HH + f * SCn + lane];
        float sq = x * x;
        #pragma unroll
        for (int off = 16; off; off >>= 1)
            sq += __shfl_xor_sync(0xffffffffu, sq, off);
        float xn = x / fmaxf(sqrtf(sq), 1e-12f);
        uint32_t hi = f2tf32(xn);
        int flat = afrag(wid, lane >> 3, (i & 7) * 4 + (lane & 3),
                         (i >> 3) + 2 * ((lane >> 2) & 1));
        AFh[flat] = hi;
        AFl[flat] = f2tf32(xn - __uint_as_float(hi));
    }

    // B: coalesced uint4 copy of precomputed interleaved fragments
    const uint4* srcB = (const uint4*)&g_cpF[(size_t)m * 16384];
    #pragma unroll
    for (int it = 0; it < 16; it++) {
        int idx = tid + it * 256;
        ((uint4*)BF)[idx] = srcB[idx];
    }
    __syncthreads();

    const float alpha = alpha_p[0];
    const float beta  = beta_p[0];

    // A-hi fragments hoisted (reused for all 4 s-chunks)
    uint4 ahv[4];
    #pragma unroll
    for (int ks = 0; ks < 4; ks++)
        ahv[ks] = ((const uint4*)AFh)[(wid * 4 + ks) * 32 + lane];

    float vb[2] = {-INFINITY, -INFINITY};
    int   sb[2] = {0, 0};

    #pragma unroll 1
    for (int cq = 0; cq < 4; cq++) {
        float4 acc[8];
        #pragma unroll
        for (int j = 0; j < 8; j++) acc[j] = make_float4(0.f, 0.f, 0.f, 0.f);

        #pragma unroll
        for (int ks = 0; ks < 4; ks++) {
            uint4 alv = ((const uint4*)AFl)[(wid * 4 + ks) * 32 + lane];
            #pragma unroll
            for (int j = 0; j < 8; j++) {
                int nt = cq * 8 + j;
                uint4 bv = ((const uint4*)BF)[(nt * 4 + ks) * 32 + lane];
                uint32_t bh[2] = {bv.x, bv.y};
                uint32_t bl[2] = {bv.z, bv.w};
                mma8(acc[j], (const uint32_t*)&ahv[ks], bh);
                mma8(acc[j], (const uint32_t*)&ahv[ks], bl);
                mma8(acc[j], (const uint32_t*)&alv,     bh);
            }
        }

        // tree argmax (depth 4; ties keep smaller s), then one running update
        #pragma unroll
        for (int r = 0; r < 2; r++) {
            float tv[8];
            int   ts[8];
            #pragma unroll
            for (int j = 0; j < 8; j++) {
                int s0 = cq * 64 + j * 8 + 2 * tg;
                float va = fmaf(alpha, r ? acc[j].z : acc[j].x, beta);
                float vc = fmaf(alpha, r ? acc[j].w : acc[j].y, beta);
                bool p = va >= vc;
                tv[j] = p ? va : vc;
                ts[j] = p ? s0 : s0 + 1;
            }
            #pragma unroll
            for (int off = 1; off < 8; off <<= 1) {
                #pragma unroll
                for (int j = 0; j < 8; j += 2 * off) {
                    bool p = tv[j] >= tv[j + off];
                    tv[j] = p ? tv[j] : tv[j + off];
                    ts[j] = p ? ts[j] : ts[j + off];
                }
            }
            if (tv[0] > vb[r]) { vb[r] = tv[0]; sb[r] = ts[0]; }
        }
    }

    // reduce argmax across the 4 tg-lanes of each quad (rows g / g+8)
    #pragma unroll
    for (int r = 0; r < 2; r++) {
        #pragma unroll
        for (int off = 1; off < 4; off <<= 1) {
            float v2 = __shfl_xor_sync(0xffffffffu, vb[r], off);
            int   s2 = __shfl_xor_sync(0xffffffffu, sb[r], off);
            if (v2 > vb[r] || (v2 == vb[r] && s2 < sb[r])) { vb[r] = v2; sb[r] = s2; }
        }
    }
    if (tg == 0) {
        int row0 = wid * 16 + g;
        smv[row0]     = 1.f / (1.f + __expf(-vb[0]));
        sms[row0]     = sb[0];
        smv[row0 + 8] = 1.f / (1.f + __expf(-vb[1]));
        sms[row0 + 8] = sb[1];
    }
    __syncthreads();

    // gather + scale + write dispatched
    const float* cvm = &g_cv[(size_t)m * SS * SCn];
    #pragma unroll
    for (int it = 0; it < 16; it++) {
        int idx = tid + it * 256;
        int row = idx >> 5, k = idx & 31;
        float out = smv[row] * __ldg(&cvm[sms[row] * SCn + k]);
        g_disp[((size_t)(n * LL + l0 + row)) * HH + f * SCn + k] = out;
    }
}

// ---------------------------------------------------------------------------
extern "C" void kernel_launch(void* const* d_in, const int* in_sizes, int n_in,
                              void* d_out, int out_size)
{
    const float* x0      = (const float*)d_in[0];
    const float* center1 = (const float*)d_in[1];
    const float* W0      = (const float*)d_in[2];
    const float* b0      = (const float*)d_in[3];
    const float* W1      = (const float*)d_in[4];
    const float* b1      = (const float*)d_in[5];
    const float* Wm      = (const float*)d_in[6];
    const float* bm      = (const float*)d_in[7];
    const float* alpha   = (const float*)d_in[8];
    const float* beta    = (const float*)d_in[9];
    float* out           = (float*)d_out;

    float* c1p;   cudaGetSymbolAddress((void**)&c1p,  g_c1);
    float* x0pp;  cudaGetSymbolAddress((void**)&x0pp, g_x0p);
    float* dispp; cudaGetSymbolAddress((void**)&dispp, g_disp);

    const int simSmem  = (4096 + 4096 + 16384) * 4 + 128 * 8;  // 99328
    const int mma3Smem = 4 * 4608 * 4;                          // 73728
    const int mma1Smem = 2 * 4608 * 4;                          // 36864
    cudaFuncSetAttribute(sim_mma, cudaFuncAttributeMaxDynamicSharedMemorySize, simSmem);
    cudaFuncSetAttribute(gemm_mma<3>, cudaFuncAttributeMaxDynamicSharedMemorySize, mma3Smem);
    cudaFuncSetAttribute(gemm_mma<1>, cudaFuncAttributeMaxDynamicSharedMemorySize, mma1Smem);

    // K1: c1 = center1 @ W1^T + b1   (1024 x 512 x 256), fp32 FFMA2
    gemm_nt<64><<<dim3(1024 / 128, H2 / 64), 256>>>(center1, W1, b1, c1p, H2);

    // K1b: normalize c_point -> interleaved tf32 fragment layout, split c_value
    center_norm_kernel<<<1024, 256>>>();

    // K2: x0p = x0 @ W0^T + b0  (3xTF32 mma.sync, 128x128 tiles, 1 wave)
    gemm_mma<3><<<dim3((NB * LL) / 128, HH / 128), 256, mma3Smem>>>(x0, W0, b0, x0pp, HH);

    // K3: sim (3xTF32 mma.sync) + tree-argmax + sigmoid + gather -> dispatched
    sim_mma<<<dim3(LL / 128, MM), 256, simSmem>>>(alpha, beta);

    // K4: out = dispatched @ Wm^T + bm  (single-pass tf32, 128x128 tiles)
    gemm_mma<1><<<dim3((NB * LL) / 128, HH / 128), 256, mma1Smem>>>(dispp, Wm, bm, out, HH);
}

// round 13
// speedup vs baseline: 1.5147x; 1.5147x over previous
#include <cuda_runtime.h>
#include <math.h>
#include <stdint.h>

// Problem constants
#define NB   4
#define LL   4096
#define SS   256
#define HH   256
#define FCn  8
#define SCn  32
#define MM   32      // NB*FCn
#define H2   512
#define KK   256     // inner dim of dense GEMMs

typedef unsigned long long u64;

// Scratch (device globals; no dynamic allocation allowed)
__device__ float    g_c1[NB * SS * H2];       // center1 @ W1^T + b1
__device__ uint32_t g_cpFH[MM * 8192];        // tf32 hi of cpN, B-fragment layout
__device__ uint32_t g_cpFL[MM * 8192];        // tf32 lo residual, B-fragment layout
__device__ float    g_cv  [MM * SS * SCn];    // c_value
__device__ float    g_x0p [NB * LL * HH];     // x0 @ W0^T + b0
__device__ float    g_disp[NB * LL * HH];     // dispatched

// ---------------------------------------------------------------------------
// PTX helpers
// ---------------------------------------------------------------------------
__device__ __forceinline__ u64 ffma2(u64 a, u64 b, u64 c) {
    u64 d;
    asm("fma.rn.f32x2 %0, %1, %2, %3;" : "=l"(d) : "l"(a), "l"(b), "l"(c));
    return d;
}
__device__ __forceinline__ u64 pack2(float x, float y) {
    u64 r;
    asm("mov.b64 %0, {%1, %2};" : "=l"(r) : "f"(x), "f"(y));
    return r;
}
__device__ __forceinline__ float2 unpack2(u64 v) {
    float2 f;
    asm("mov.b64 {%0, %1}, %2;" : "=f"(f.x), "=f"(f.y) : "l"(v));
    return f;
}
__device__ __forceinline__ uint32_t f2tf32(float x) {
    uint32_t r;
    asm("cvt.rna.tf32.f32 %0, %1;" : "=r"(r) : "f"(x));
    return r;
}
// m16n8k8 tf32 warp MMA, D += A*B (fp32 accum)
__device__ __forceinline__ void mma8(float4& d, const uint32_t* a, const uint32_t* b) {
    asm("mma.sync.aligned.m16n8k8.row.col.f32.tf32.tf32.f32 "
        "{%0,%1,%2,%3}, {%4,%5,%6,%7}, {%8,%9}, {%0,%1,%2,%3};"
        : "+f"(d.x), "+f"(d.y), "+f"(d.z), "+f"(d.w)
        : "r"(a[0]), "r"(a[1]), "r"(a[2]), "r"(a[3]), "r"(b[0]), "r"(b[1]));
}

// Fragment-layout flat indices (units: uint32 words).
// A-frag: [rowtile(16 rows)][ks][lane][4 regs]
// B-frag: [ntile(8 cols)][ks][lane][2 regs]
__device__ __forceinline__ int afrag(int rowtile, int ks, int lane, int reg) {
    return ((rowtile * 4 + ks) * 32 + lane) * 4 + reg;
}
__device__ __forceinline__ int bfrag(int ntile, int ks, int lane, int reg) {
    return ((ntile * 4 + ks) * 32 + lane) * 2 + reg;
}

// ---------------------------------------------------------------------------
// Tensor-core GEMM via mma.sync tf32 (row-major stride-36 smem, proven R9/R11):
//   C[R][Hout] = A[R][256] @ B[Hout][256]^T + bias
// NPASS=1: plain tf32 — K4.  NPASS=3: hi/lo compensation (~fp32) — K2.
// Block tile 128x128, 8 warps: 4m x 2n; warp tile 32m x 64n.
// ---------------------------------------------------------------------------
template<int NPASS>
__global__ __launch_bounds__(256, 2) void gemm_mma(
    const float* __restrict__ A, const float* __restrict__ B,
    const float* __restrict__ bias, float* __restrict__ C, int Hout)
{
    extern __shared__ __align__(16) uint32_t msm[];
    uint32_t* Ah = msm;                                    // [128][36]
    uint32_t* Al = Ah + 4608;                              // NPASS==3 only
    uint32_t* Bh = (NPASS == 3) ? (Al + 4608) : (Ah + 4608);  // [128][36]
    uint32_t* Bl = Bh + 4608;                              // NPASS==3 only

    const int tid  = threadIdx.x;
    const int wid  = tid >> 5;
    const int lane = tid & 31;
    const int g  = lane >> 2;
    const int tg = lane & 3;
    const int mbase = (wid & 3) * 32;
    const int nbase = (wid >> 2) * 64;
    const int r0 = blockIdx.x * 128;
    const int h0 = blockIdx.y * 128;

    float4 acc[2][8];
    #pragma unroll
    for (int i = 0; i < 2; i++)
        #pragma unroll
        for (int j = 0; j < 8; j++) acc[i][j] = make_float4(0.f, 0.f, 0.f, 0.f);

    for (int c = 0; c < 8; c++) {
        __syncthreads();
        #pragma unroll
        for (int it = 0; it < 4; it++) {
            int idx = tid + it * 256;
            int row = idx >> 3, j = idx & 7;
            float4 v = *(const float4*)&A[(size_t)(r0 + row) * 256 + c * 32 + j * 4];
            uint32_t base = row * 36 + j * 4;
            float xs[4] = {v.x, v.y, v.z, v.w};
            #pragma unroll
            for (int t = 0; t < 4; t++) {
                uint32_t hi = f2tf32(xs[t]);
                Ah[base + t] = hi;
                if constexpr (NPASS == 3)
                    Al[base + t] = f2tf32(xs[t] - __uint_as_float(hi));
            }
        }
        #pragma unroll
        for (int it = 0; it < 4; it++) {
            int idx = tid + it * 256;
            int row = idx >> 3, j = idx & 7;
            float4 v = *(const float4*)&B[(size_t)(h0 + row) * 256 + c * 32 + j * 4];
            uint32_t base = row * 36 + j * 4;
            float xs[4] = {v.x, v.y, v.z, v.w};
            #pragma unroll
            for (int t = 0; t < 4; t++) {
                uint32_t hi = f2tf32(xs[t]);
                Bh[base + t] = hi;
                if constexpr (NPASS == 3)
                    Bl[base + t] = f2tf32(xs[t] - __uint_as_float(hi));
            }
        }
        __syncthreads();

        #pragma unroll
        for (int ks = 0; ks < 4; ks++) {
            const int k0 = ks * 8;
            uint32_t ah[2][4], al[2][4];
            #pragma unroll
            for (int i = 0; i < 2; i++) {
                uint32_t rb = (mbase + i * 16 + g) * 36 + k0 + tg;
                ah[i][0] = Ah[rb];
                ah[i][1] = Ah[rb + 8 * 36];
                ah[i][2] = Ah[rb + 4];
                ah[i][3] = Ah[rb + 8 * 36 + 4];
                if constexpr (NPASS == 3) {
                    al[i][0] = Al[rb];
                    al[i][1] = Al[rb + 8 * 36];
                    al[i][2] = Al[rb + 4];
                    al[i][3] = Al[rb + 8 * 36 + 4];
                }
            }
            #pragma unroll
            for (int j = 0; j < 8; j++) {
                uint32_t rb = (nbase + j * 8 + g) * 36 + k0 + tg;
                uint32_t bh[2] = {Bh[rb], Bh[rb + 4]};
                #pragma unroll
                for (int i = 0; i < 2; i++)
                    mma8(acc[i][j], ah[i], bh);
                if constexpr (NPASS == 3) {
                    uint32_t bl[2] = {Bl[rb], Bl[rb + 4]};
                    #pragma unroll
                    for (int i = 0; i < 2; i++) {
                        mma8(acc[i][j], ah[i], bl);
                        mma8(acc[i][j], al[i], bh);
                    }
                }
            }
        }
    }

    #pragma unroll
    for (int j = 0; j < 8; j++) {
        int col = h0 + nbase + j * 8 + 2 * tg;
        float2 bb = *(const float2*)&bias[col];
        #pragma unroll
        for (int i = 0; i < 2; i++) {
            int row = r0 + mbase + i * 16 + g;
            float2 o0 = make_float2(acc[i][j].x + bb.x, acc[i][j].y + bb.y);
            float2 o1 = make_float2(acc[i][j].z + bb.x, acc[i][j].w + bb.y);
            *(float2*)&C[(size_t)row * Hout + col] = o0;
            *(float2*)&C[(size_t)(row + 8) * Hout + col] = o1;
        }
    }
}

// ---------------------------------------------------------------------------
// Dense fp32 GEMM (K1 only)
// ---------------------------------------------------------------------------
template<int NT>
__global__ __launch_bounds__(256, 2) void gemm_nt(
    const float* __restrict__ A, const float* __restrict__ B,
    const float* __restrict__ bias, float* __restrict__ C, int Hout)
{
    constexpr int SN = NT / 16;
    __shared__ __align__(16) float as[32][132];
    __shared__ __align__(16) float bs[32][NT + 4];

    const int r0 = blockIdx.x * 128;
    const int h0 = blockIdx.y * NT;
    const int tid = threadIdx.x;
    const int tc = tid & 15;
    const int tr = tid >> 4;
    const int k4 = (tid & 7) * 4;
    const int rl = tid >> 3;

    u64 acc[4][SN];
    #pragma unroll
    for (int p = 0; p < 4; p++)
        #pragma unroll
        for (int j = 0; j < SN; j++) acc[p][j] = 0ull;

    for (int k0 = 0; k0 < KK; k0 += 32) {
        #pragma unroll
        for (int it = 0; it < 4; it++) {
            int row = rl + it * 32;
            float4 v = *(const float4*)&A[(size_t)(r0 + row) * KK + k0 + k4];
            as[k4 + 0][row] = v.x;
            as[k4 + 1][row] = v.y;
            as[k4 + 2][row] = v.z;
            as[k4 + 3][row] = v.w;
        }
        #pragma unroll
        for (int it = 0; it < NT / 32; it++) {
            int h = rl + it * 32;
            float4 v = *(const float4*)&B[(size_t)(h0 + h) * KK + k0 + k4];
            bs[k4 + 0][h] = v.x;
            bs[k4 + 1][h] = v.y;
            bs[k4 + 2][h] = v.z;
            bs[k4 + 3][h] = v.w;
        }
        __syncthreads();

        #pragma unroll 8
        for (int kk = 0; kk < 32; kk++) {
            ulonglong2 a01 = *(const ulonglong2*)&as[kk][tr * 8];
            ulonglong2 a23 = *(const ulonglong2*)&as[kk][tr * 8 + 4];
            u64 ap[4] = {a01.x, a01.y, a23.x, a23.y};
            #pragma unroll
            for (int jq = 0; jq < SN / 4; jq++) {
                float4 bv = *(const float4*)&bs[kk][tc * SN + jq * 4];
                u64 b0 = pack2(bv.x, bv.x);
                u64 b1 = pack2(bv.y, bv.y);
                u64 b2 = pack2(bv.z, bv.z);
                u64 b3 = pack2(bv.w, bv.w);
                #pragma unroll
                for (int p = 0; p < 4; p++) {
                    acc[p][jq * 4 + 0] = ffma2(ap[p], b0, acc[p][jq * 4 + 0]);
                    acc[p][jq * 4 + 1] = ffma2(ap[p], b1, acc[p][jq * 4 + 1]);
                    acc[p][jq * 4 + 2] = ffma2(ap[p], b2, acc[p][jq * 4 + 2]);
                    acc[p][jq * 4 + 3] = ffma2(ap[p], b3, acc[p][jq * 4 + 3]);
                }
            }
        }
        __syncthreads();
    }

    #pragma unroll
    for (int jq = 0; jq < SN / 4; jq++) {
        float4 bb = *(const float4*)&bias[h0 + tc * SN + jq * 4];
        #pragma unroll
        for (int p = 0; p < 4; p++) {
            float2 f0 = unpack2(acc[p][jq * 4 + 0]);
            float2 f1 = unpack2(acc[p][jq * 4 + 1]);
            float2 f2 = unpack2(acc[p][jq * 4 + 2]);
            float2 f3 = unpack2(acc[p][jq * 4 + 3]);
            int row0 = r0 + tr * 8 + 2 * p;
            float4 o0 = make_float4(f0.x + bb.x, f1.x + bb.y, f2.x + bb.z, f3.x + bb.w);
            float4 o1 = make_float4(f0.y + bb.x, f1.y + bb.y, f2.y + bb.z, f3.y + bb.w);
            *(float4*)&C[(size_t)row0 * Hout + h0 + tc * SN + jq * 4] = o0;
            *(float4*)&C[(size_t)(row0 + 1) * Hout + h0 + tc * SN + jq * 4] = o1;
        }
    }
}

// ---------------------------------------------------------------------------
// Split c1 -> c_point (l2-normalized, tf32 hi/lo in B-fragment layout) / c_value.
// ---------------------------------------------------------------------------
__global__ __launch_bounds__(256) void center_norm_kernel()
{
    int w    = (blockIdx.x * blockDim.x + threadIdx.x) >> 5;
    int lane = threadIdx.x & 31;
    int m = w >> 8;
    int s = w & 255;
    int n = m >> 3, f = m & 7;

    const float* row = &g_c1[((size_t)(n * SS + s)) * H2 + f * 64];
    float p = row[lane];
    float v = row[32 + lane];

    float sq = p * p;
    #pragma unroll
    for (int off = 16; off; off >>= 1)
        sq += __shfl_xor_sync(0xffffffffu, sq, off);

    float d = fmaxf(sqrtf(sq), 1e-12f);
    float pn = p / d;
    uint32_t hi = f2tf32(pn);
    uint32_t lo = f2tf32(pn - __uint_as_float(hi));

    int flat = bfrag(s >> 3, lane >> 3, (s & 7) * 4 + (lane & 3), (lane >> 2) & 1);
    g_cpFH[(size_t)m * 8192 + flat] = hi;
    g_cpFL[(size_t)m * 8192 + flat] = lo;
    g_cv[((size_t)(m * SS + s)) * SCn + lane] = v;
}

// ---------------------------------------------------------------------------
// Fused sim (3xTF32 mma.sync) + argmax + sigmoid + gather. (R10 version, 69us)
// Fragment-major smem; B is a straight float4 copy of g_cpFH/FL.
// block = (m, 128-l tile), 256 threads, 8 warps x 16 rows.
// ---------------------------------------------------------------------------
__global__ __launch_bounds__(256, 2) void sim_mma(
    const float* __restrict__ alpha_p, const float* __restrict__ beta_p)
{
    extern __shared__ __align__(16) uint32_t ssm[];
    uint32_t* AFh = ssm;                 // 8rt*4*32*4 = 4096
    uint32_t* AFl = AFh + 4096;
    uint32_t* BFh = AFl + 4096;          // 32nt*4*32*2 = 8192
    uint32_t* BFl = BFh + 8192;
    float*    smv = (float*)(BFl + 8192);   // [128]
    int*      sms = (int*)(smv + 128);      // [128]

    const int m  = blockIdx.y;
    const int n  = m >> 3, f = m & 7;
    const int l0 = blockIdx.x * 128;
    const int tid  = threadIdx.x;
    const int wid  = tid >> 5;
    const int lane = tid & 31;
    const int g  = lane >> 2;
    const int tg = lane & 3;

    // A: load x0p rows, l2-normalize, tf32 hi/lo -> fragment layout
    #pragma unroll 4
    for (int i = 0; i < 16; i++) {
        int row = wid * 16 + i;
        float x = g_x0p[((size_t)(n * LL + l0 + row)) * HH + f * SCn + lane];
        float sq = x * x;
        #pragma unroll
        for (int off = 16; off; off >>= 1)
            sq += __shfl_xor_sync(0xffffffffu, sq, off);
        float xn = x / fmaxf(sqrtf(sq), 1e-12f);
        uint32_t hi = f2tf32(xn);
        int flat = afrag(wid, lane >> 3, (i & 7) * 4 + (lane & 3),
                         (i >> 3) + 2 * ((lane >> 2) & 1));
        AFh[flat] = hi;
        AFl[flat] = f2tf32(xn - __uint_as_float(hi));
    }

    // B: coalesced float4 copy of precomputed fragment layout
    const uint4* srcH = (const uint4*)&g_cpFH[(size_t)m * 8192];
    const uint4* srcL = (const uint4*)&g_cpFL[(size_t)m * 8192];
    #pragma unroll
    for (int it = 0; it < 8; it++) {
        int idx = tid + it * 256;
        ((uint4*)BFh)[idx] = srcH[idx];
        ((uint4*)BFl)[idx] = srcL[idx];
    }
    __syncthreads();

    const float alpha = alpha_p[0];
    const float beta  = beta_p[0];

    // A-hi fragments hoisted (reused for all 4 s-chunks)
    uint4 ahv[4];
    #pragma unroll
    for (int ks = 0; ks < 4; ks++)
        ahv[ks] = ((const uint4*)AFh)[(wid * 4 + ks) * 32 + lane];

    float vb[2] = {-INFINITY, -INFINITY};
    int   sb[2] = {0, 0};

    #pragma unroll 1
    for (int cq = 0; cq < 4; cq++) {
        float4 acc[8];
        #pragma unroll
        for (int j = 0; j < 8; j++) acc[j] = make_float4(0.f, 0.f, 0.f, 0.f);

        #pragma unroll
        for (int ks = 0; ks < 4; ks++) {
            uint4 alv = ((const uint4*)AFl)[(wid * 4 + ks) * 32 + lane];
            #pragma unroll
            for (int j = 0; j < 8; j++) {
                int nt = cq * 8 + j;
                uint2 bh = ((const uint2*)BFh)[(nt * 4 + ks) * 32 + lane];
                uint2 bl = ((const uint2*)BFl)[(nt * 4 + ks) * 32 + lane];
                mma8(acc[j], (const uint32_t*)&ahv[ks], (const uint32_t*)&bh);
                mma8(acc[j], (const uint32_t*)&ahv[ks], (const uint32_t*)&bl);
                mma8(acc[j], (const uint32_t*)&alv,     (const uint32_t*)&bh);
            }
        }

        // running affine argmax (ascending s, strict >)
        const int sbase = cq * 64;
        #pragma unroll
        for (int j = 0; j < 8; j++) {
            int s0 = sbase + j * 8 + 2 * tg;
            float v0 = fmaf(alpha, acc[j].x, beta);
            float v1 = fmaf(alpha, acc[j].y, beta);
            float v2 = fmaf(alpha, acc[j].z, beta);
            float v3 = fmaf(alpha, acc[j].w, beta);
            if (v0 > vb[0]) { vb[0] = v0; sb[0] = s0; }
            if (v1 > vb[0]) { vb[0] = v1; sb[0] = s0 + 1; }
            if (v2 > vb[1]) { vb[1] = v2; sb[1] = s0; }
            if (v3 > vb[1]) { vb[1] = v3; sb[1] = s0 + 1; }
        }
    }

    // reduce argmax across the 4 tg-lanes of each quad (rows g / g+8)
    #pragma unroll
    for (int r = 0; r < 2; r++) {
        #pragma unroll
        for (int off = 1; off < 4; off <<= 1) {
            float v2 = __shfl_xor_sync(0xffffffffu, vb[r], off);
            int   s2 = __shfl_xor_sync(0xffffffffu, sb[r], off);
            if (v2 > vb[r] || (v2 == vb[r] && s2 < sb[r])) { vb[r] = v2; sb[r] = s2; }
        }
    }
    if (tg == 0) {
        int row0 = wid * 16 + g;
        smv[row0]     = 1.f / (1.f + __expf(-vb[0]));
        sms[row0]     = sb[0];
        smv[row0 + 8] = 1.f / (1.f + __expf(-vb[1]));
        sms[row0 + 8] = sb[1];
    }
    __syncthreads();

    // gather + scale + write dispatched
    const float* cvm = &g_cv[(size_t)m * SS * SCn];
    #pragma unroll
    for (int it = 0; it < 16; it++) {
        int idx = tid + it * 256;
        int row = idx >> 5, k = idx & 31;
        float out = smv[row] * __ldg(&cvm[sms[row] * SCn + k]);
        g_disp[((size_t)(n * LL + l0 + row)) * HH + f * SCn + k] = out;
    }
}

// ---------------------------------------------------------------------------
extern "C" void kernel_launch(void* const* d_in, const int* in_sizes, int n_in,
                              void* d_out, int out_size)
{
    const float* x0      = (const float*)d_in[0];
    const float* center1 = (const float*)d_in[1];
    const float* W0      = (const float*)d_in[2];
    const float* b0      = (const float*)d_in[3];
    const float* W1      = (const float*)d_in[4];
    const float* b1      = (const float*)d_in[5];
    const float* Wm      = (const float*)d_in[6];
    const float* bm      = (const float*)d_in[7];
    const float* alpha   = (const float*)d_in[8];
    const float* beta    = (const float*)d_in[9];
    float* out           = (float*)d_out;

    float* c1p;   cudaGetSymbolAddress((void**)&c1p,  g_c1);
    float* x0pp;  cudaGetSymbolAddress((void**)&x0pp, g_x0p);
    float* dispp; cudaGetSymbolAddress((void**)&dispp, g_disp);

    const int simSmem  = (2 * 4096 + 2 * 8192) * 4 + 128 * 8;  // 99328
    const int mma3Smem = 4 * 4608 * 4;                          // 73728
    const int mma1Smem = 2 * 4608 * 4;                          // 36864
    cudaFuncSetAttribute(sim_mma, cudaFuncAttributeMaxDynamicSharedMemorySize, simSmem);
    cudaFuncSetAttribute(gemm_mma<3>, cudaFuncAttributeMaxDynamicSharedMemorySize, mma3Smem);
    cudaFuncSetAttribute(gemm_mma<1>, cudaFuncAttributeMaxDynamicSharedMemorySize, mma1Smem);

    // Fork a side stream so the center chain (K1 -> norm) overlaps K2.
    cudaStream_t s2;
    cudaStreamCreateWithFlags(&s2, cudaStreamNonBlocking);
    cudaEvent_t e0, e1;
    cudaEventCreateWithFlags(&e0, cudaEventDisableTiming);
    cudaEventCreateWithFlags(&e1, cudaEventDisableTiming);

    cudaEventRecord(e0, 0);
    cudaStreamWaitEvent(s2, e0, 0);

    // side stream: K1 (centers) + K1b (normalize/split)
    gemm_nt<64><<<dim3(1024 / 128, H2 / 64), 256, 0, s2>>>(center1, W1, b1, c1p, H2);
    center_norm_kernel<<<1024, 256, 0, s2>>>();
    cudaEventRecord(e1, s2);

    // main stream: K2 (x0 projection) runs concurrently with the center chain
    gemm_mma<3><<<dim3((NB * LL) / 128, HH / 128), 256, mma3Smem>>>(x0, W0, b0, x0pp, HH);

    // join: sim needs both x0p and the centers
    cudaStreamWaitEvent(0, e1, 0);

    // K3: sim (3xTF32 mma.sync) + argmax + sigmoid + gather -> dispatched
    sim_mma<<<dim3(LL / 128, MM), 256, simSmem>>>(alpha, beta);

    // K4: out = dispatched @ Wm^T + bm  (single-pass tf32, 128x128 tiles)
    gemm_mma<1><<<dim3((NB * LL) / 128, HH / 128), 256, mma1Smem>>>(dispp, Wm, bm, out, HH);
}

// round 14
// speedup vs baseline: 1.5441x; 1.0194x over previous
#include <cuda_runtime.h>
#include <math.h>
#include <stdint.h>

// Problem constants
#define NB   4
#define LL   4096
#define SS   256
#define HH   256
#define FCn  8
#define SCn  32
#define MM   32      // NB*FCn
#define H2   512
#define KK   256     // inner dim of dense GEMMs

typedef unsigned long long u64;

// Scratch (device globals; no dynamic allocation allowed)
__device__ float    g_c1[NB * SS * H2];       // center1 @ W1^T + b1
__device__ uint32_t g_cpFH[MM * 8192];        // tf32 hi of cpN, B-fragment layout
__device__ uint32_t g_cpFL[MM * 8192];        // tf32 lo residual, B-fragment layout
__device__ float    g_cv  [MM * SS * SCn];    // c_value
__device__ float    g_x0p [NB * LL * HH];     // x0 @ W0^T + b0
__device__ float    g_disp[NB * LL * HH];     // dispatched

// ---------------------------------------------------------------------------
// PTX helpers
// ---------------------------------------------------------------------------
__device__ __forceinline__ u64 ffma2(u64 a, u64 b, u64 c) {
    u64 d;
    asm("fma.rn.f32x2 %0, %1, %2, %3;" : "=l"(d) : "l"(a), "l"(b), "l"(c));
    return d;
}
__device__ __forceinline__ u64 pack2(float x, float y) {
    u64 r;
    asm("mov.b64 %0, {%1, %2};" : "=l"(r) : "f"(x), "f"(y));
    return r;
}
__device__ __forceinline__ float2 unpack2(u64 v) {
    float2 f;
    asm("mov.b64 {%0, %1}, %2;" : "=f"(f.x), "=f"(f.y) : "l"(v));
    return f;
}
__device__ __forceinline__ uint32_t f2tf32(float x) {
    uint32_t r;
    asm("cvt.rna.tf32.f32 %0, %1;" : "=r"(r) : "f"(x));
    return r;
}
// m16n8k8 tf32 warp MMA, D += A*B (fp32 accum)
__device__ __forceinline__ void mma8(float4& d, const uint32_t* a, const uint32_t* b) {
    asm("mma.sync.aligned.m16n8k8.row.col.f32.tf32.tf32.f32 "
        "{%0,%1,%2,%3}, {%4,%5,%6,%7}, {%8,%9}, {%0,%1,%2,%3};"
        : "+f"(d.x), "+f"(d.y), "+f"(d.z), "+f"(d.w)
        : "r"(a[0]), "r"(a[1]), "r"(a[2]), "r"(a[3]), "r"(b[0]), "r"(b[1]));
}

// Fragment-layout flat indices (units: uint32 words).
// A-frag: [rowtile(16 rows)][ks][lane][4 regs]
// B-frag: [ntile(8 cols)][ks][lane][2 regs]
__device__ __forceinline__ int afrag(int rowtile, int ks, int lane, int reg) {
    return ((rowtile * 4 + ks) * 32 + lane) * 4 + reg;
}
__device__ __forceinline__ int bfrag(int ntile, int ks, int lane, int reg) {
    return ((ntile * 4 + ks) * 32 + lane) * 2 + reg;
}

// ---------------------------------------------------------------------------
// Tensor-core GEMM via mma.sync tf32 (row-major stride-36 smem):
//   C[R][Hout] = A[R][256] @ B[Hout][256]^T + bias
// NPASS=1: plain tf32 — K4.  NPASS=3: hi/lo compensation (~fp32) — K2.
// Block tile 128x128, 8 warps: 4m x 2n; warp tile 32m x 64n.
// 3-pass loop is PASS-MAJOR: consecutive MMAs hit different accumulators.
// ---------------------------------------------------------------------------
template<int NPASS>
__global__ __launch_bounds__(256, 2) void gemm_mma(
    const float* __restrict__ A, const float* __restrict__ B,
    const float* __restrict__ bias, float* __restrict__ C, int Hout)
{
    extern __shared__ __align__(16) uint32_t msm[];
    uint32_t* Ah = msm;                                    // [128][36]
    uint32_t* Al = Ah + 4608;                              // NPASS==3 only
    uint32_t* Bh = (NPASS == 3) ? (Al + 4608) : (Ah + 4608);  // [128][36]
    uint32_t* Bl = Bh + 4608;                              // NPASS==3 only

    const int tid  = threadIdx.x;
    const int wid  = tid >> 5;
    const int lane = tid & 31;
    const int g  = lane >> 2;
    const int tg = lane & 3;
    const int mbase = (wid & 3) * 32;
    const int nbase = (wid >> 2) * 64;
    const int r0 = blockIdx.x * 128;
    const int h0 = blockIdx.y * 128;

    float4 acc[2][8];
    #pragma unroll
    for (int i = 0; i < 2; i++)
        #pragma unroll
        for (int j = 0; j < 8; j++) acc[i][j] = make_float4(0.f, 0.f, 0.f, 0.f);

    for (int c = 0; c < 8; c++) {
        __syncthreads();
        #pragma unroll
        for (int it = 0; it < 4; it++) {
            int idx = tid + it * 256;
            int row = idx >> 3, j = idx & 7;
            float4 v = *(const float4*)&A[(size_t)(r0 + row) * 256 + c * 32 + j * 4];
            uint32_t base = row * 36 + j * 4;
            float xs[4] = {v.x, v.y, v.z, v.w};
            #pragma unroll
            for (int t = 0; t < 4; t++) {
                uint32_t hi = f2tf32(xs[t]);
                Ah[base + t] = hi;
                if constexpr (NPASS == 3)
                    Al[base + t] = f2tf32(xs[t] - __uint_as_float(hi));
            }
        }
        #pragma unroll
        for (int it = 0; it < 4; it++) {
            int idx = tid + it * 256;
            int row = idx >> 3, j = idx & 7;
            float4 v = *(const float4*)&B[(size_t)(h0 + row) * 256 + c * 32 + j * 4];
            uint32_t base = row * 36 + j * 4;
            float xs[4] = {v.x, v.y, v.z, v.w};
            #pragma unroll
            for (int t = 0; t < 4; t++) {
                uint32_t hi = f2tf32(xs[t]);
                Bh[base + t] = hi;
                if constexpr (NPASS == 3)
                    Bl[base + t] = f2tf32(xs[t] - __uint_as_float(hi));
            }
        }
        __syncthreads();

        #pragma unroll
        for (int ks = 0; ks < 4; ks++) {
            const int k0 = ks * 8;
            uint32_t ah[2][4], al[2][4];
            #pragma unroll
            for (int i = 0; i < 2; i++) {
                uint32_t rb = (mbase + i * 16 + g) * 36 + k0 + tg;
                ah[i][0] = Ah[rb];
                ah[i][1] = Ah[rb + 8 * 36];
                ah[i][2] = Ah[rb + 4];
                ah[i][3] = Ah[rb + 8 * 36 + 4];
                if constexpr (NPASS == 3) {
                    al[i][0] = Al[rb];
                    al[i][1] = Al[rb + 8 * 36];
                    al[i][2] = Al[rb + 4];
                    al[i][3] = Al[rb + 8 * 36 + 4];
                }
            }
            // pass 1: hi * bh  (independent accs back-to-back)
            #pragma unroll
            for (int j = 0; j < 8; j++) {
                uint32_t rb = (nbase + j * 8 + g) * 36 + k0 + tg;
                uint32_t bh[2] = {Bh[rb], Bh[rb + 4]};
                mma8(acc[0][j], ah[0], bh);
                mma8(acc[1][j], ah[1], bh);
            }
            if constexpr (NPASS == 3) {
                // pass 2: hi * bl
                #pragma unroll
                for (int j = 0; j < 8; j++) {
                    uint32_t rb = (nbase + j * 8 + g) * 36 + k0 + tg;
                    uint32_t bl[2] = {Bl[rb], Bl[rb + 4]};
                    mma8(acc[0][j], ah[0], bl);
                    mma8(acc[1][j], ah[1], bl);
                }
                // pass 3: lo * bh
                #pragma unroll
                for (int j = 0; j < 8; j++) {
                    uint32_t rb = (nbase + j * 8 + g) * 36 + k0 + tg;
                    uint32_t bh[2] = {Bh[rb], Bh[rb + 4]};
                    mma8(acc[0][j], al[0], bh);
                    mma8(acc[1][j], al[1], bh);
                }
            }
        }
    }

    #pragma unroll
    for (int j = 0; j < 8; j++) {
        int col = h0 + nbase + j * 8 + 2 * tg;
        float2 bb = *(const float2*)&bias[col];
        #pragma unroll
        for (int i = 0; i < 2; i++) {
            int row = r0 + mbase + i * 16 + g;
            float2 o0 = make_float2(acc[i][j].x + bb.x, acc[i][j].y + bb.y);
            float2 o1 = make_float2(acc[i][j].z + bb.x, acc[i][j].w + bb.y);
            *(float2*)&C[(size_t)row * Hout + col] = o0;
            *(float2*)&C[(size_t)(row + 8) * Hout + col] = o1;
        }
    }
}

// ---------------------------------------------------------------------------
// Dense fp32 GEMM (K1 only)
// ---------------------------------------------------------------------------
template<int NT>
__global__ __launch_bounds__(256, 2) void gemm_nt(
    const float* __restrict__ A, const float* __restrict__ B,
    const float* __restrict__ bias, float* __restrict__ C, int Hout)
{
    constexpr int SN = NT / 16;
    __shared__ __align__(16) float as[32][132];
    __shared__ __align__(16) float bs[32][NT + 4];

    const int r0 = blockIdx.x * 128;
    const int h0 = blockIdx.y * NT;
    const int tid = threadIdx.x;
    const int tc = tid & 15;
    const int tr = tid >> 4;
    const int k4 = (tid & 7) * 4;
    const int rl = tid >> 3;

    u64 acc[4][SN];
    #pragma unroll
    for (int p = 0; p < 4; p++)
        #pragma unroll
        for (int j = 0; j < SN; j++) acc[p][j] = 0ull;

    for (int k0 = 0; k0 < KK; k0 += 32) {
        #pragma unroll
        for (int it = 0; it < 4; it++) {
            int row = rl + it * 32;
            float4 v = *(const float4*)&A[(size_t)(r0 + row) * KK + k0 + k4];
            as[k4 + 0][row] = v.x;
            as[k4 + 1][row] = v.y;
            as[k4 + 2][row] = v.z;
            as[k4 + 3][row] = v.w;
        }
        #pragma unroll
        for (int it = 0; it < NT / 32; it++) {
            int h = rl + it * 32;
            float4 v = *(const float4*)&B[(size_t)(h0 + h) * KK + k0 + k4];
            bs[k4 + 0][h] = v.x;
            bs[k4 + 1][h] = v.y;
            bs[k4 + 2][h] = v.z;
            bs[k4 + 3][h] = v.w;
        }
        __syncthreads();

        #pragma unroll 8
        for (int kk = 0; kk < 32; kk++) {
            ulonglong2 a01 = *(const ulonglong2*)&as[kk][tr * 8];
            ulonglong2 a23 = *(const ulonglong2*)&as[kk][tr * 8 + 4];
            u64 ap[4] = {a01.x, a01.y, a23.x, a23.y};
            #pragma unroll
            for (int jq = 0; jq < SN / 4; jq++) {
                float4 bv = *(const float4*)&bs[kk][tc * SN + jq * 4];
                u64 b0 = pack2(bv.x, bv.x);
                u64 b1 = pack2(bv.y, bv.y);
                u64 b2 = pack2(bv.z, bv.z);
                u64 b3 = pack2(bv.w, bv.w);
                #pragma unroll
                for (int p = 0; p < 4; p++) {
                    acc[p][jq * 4 + 0] = ffma2(ap[p], b0, acc[p][jq * 4 + 0]);
                    acc[p][jq * 4 + 1] = ffma2(ap[p], b1, acc[p][jq * 4 + 1]);
                    acc[p][jq * 4 + 2] = ffma2(ap[p], b2, acc[p][jq * 4 + 2]);
                    acc[p][jq * 4 + 3] = ffma2(ap[p], b3, acc[p][jq * 4 + 3]);
                }
            }
        }
        __syncthreads();
    }

    #pragma unroll
    for (int jq = 0; jq < SN / 4; jq++) {
        float4 bb = *(const float4*)&bias[h0 + tc * SN + jq * 4];
        #pragma unroll
        for (int p = 0; p < 4; p++) {
            float2 f0 = unpack2(acc[p][jq * 4 + 0]);
            float2 f1 = unpack2(acc[p][jq * 4 + 1]);
            float2 f2 = unpack2(acc[p][jq * 4 + 2]);
            float2 f3 = unpack2(acc[p][jq * 4 + 3]);
            int row0 = r0 + tr * 8 + 2 * p;
            float4 o0 = make_float4(f0.x + bb.x, f1.x + bb.y, f2.x + bb.z, f3.x + bb.w);
            float4 o1 = make_float4(f0.y + bb.x, f1.y + bb.y, f2.y + bb.z, f3.y + bb.w);
            *(float4*)&C[(size_t)row0 * Hout + h0 + tc * SN + jq * 4] = o0;
            *(float4*)&C[(size_t)(row0 + 1) * Hout + h0 + tc * SN + jq * 4] = o1;
        }
    }
}

// ---------------------------------------------------------------------------
// Split c1 -> c_point (l2-normalized, tf32 hi/lo in B-fragment layout) / c_value.
// ---------------------------------------------------------------------------
__global__ __launch_bounds__(256) void center_norm_kernel()
{
    int w    = (blockIdx.x * blockDim.x + threadIdx.x) >> 5;
    int lane = threadIdx.x & 31;
    int m = w >> 8;
    int s = w & 255;
    int n = m >> 3, f = m & 7;

    const float* row = &g_c1[((size_t)(n * SS + s)) * H2 + f * 64];
    float p = row[lane];
    float v = row[32 + lane];

    float sq = p * p;
    #pragma unroll
    for (int off = 16; off; off >>= 1)
        sq += __shfl_xor_sync(0xffffffffu, sq, off);

    float d = fmaxf(sqrtf(sq), 1e-12f);
    float pn = p / d;
    uint32_t hi = f2tf32(pn);
    uint32_t lo = f2tf32(pn - __uint_as_float(hi));

    int flat = bfrag(s >> 3, lane >> 3, (s & 7) * 4 + (lane & 3), (lane >> 2) & 1);
    g_cpFH[(size_t)m * 8192 + flat] = hi;
    g_cpFL[(size_t)m * 8192 + flat] = lo;
    g_cv[((size_t)(m * SS + s)) * SCn + lane] = v;
}

// ---------------------------------------------------------------------------
// Fused sim (3xTF32 mma.sync, PASS-MAJOR) + argmax + sigmoid + gather.
// Fragment-major smem; B is a straight float4 copy of g_cpFH/FL.
// block = (m, 128-l tile), 256 threads, 8 warps x 16 rows.
// ---------------------------------------------------------------------------
__global__ __launch_bounds__(256, 2) void sim_mma(
    const float* __restrict__ alpha_p, const float* __restrict__ beta_p)
{
    extern __shared__ __align__(16) uint32_t ssm[];
    uint32_t* AFh = ssm;                 // 8rt*4*32*4 = 4096
    uint32_t* AFl = AFh + 4096;
    uint32_t* BFh = AFl + 4096;          // 32nt*4*32*2 = 8192
    uint32_t* BFl = BFh + 8192;
    float*    smv = (float*)(BFl + 8192);   // [128]
    int*      sms = (int*)(smv + 128);      // [128]

    const int m  = blockIdx.y;
    const int n  = m >> 3, f = m & 7;
    const int l0 = blockIdx.x * 128;
    const int tid  = threadIdx.x;
    const int wid  = tid >> 5;
    const int lane = tid & 31;
    const int g  = lane >> 2;
    const int tg = lane & 3;

    // A: load x0p rows, l2-normalize, tf32 hi/lo -> fragment layout
    #pragma unroll 4
    for (int i = 0; i < 16; i++) {
        int row = wid * 16 + i;
        float x = g_x0p[((size_t)(n * LL + l0 + row)) * HH + f * SCn + lane];
        float sq = x * x;
        #pragma unroll
        for (int off = 16; off; off >>= 1)
            sq += __shfl_xor_sync(0xffffffffu, sq, off);
        float xn = x / fmaxf(sqrtf(sq), 1e-12f);
        uint32_t hi = f2tf32(xn);
        int flat = afrag(wid, lane >> 3, (i & 7) * 4 + (lane & 3),
                         (i >> 3) + 2 * ((lane >> 2) & 1));
        AFh[flat] = hi;
        AFl[flat] = f2tf32(xn - __uint_as_float(hi));
    }

    // B: coalesced float4 copy of precomputed fragment layout
    const uint4* srcH = (const uint4*)&g_cpFH[(size_t)m * 8192];
    const uint4* srcL = (const uint4*)&g_cpFL[(size_t)m * 8192];
    #pragma unroll
    for (int it = 0; it < 8; it++) {
        int idx = tid + it * 256;
        ((uint4*)BFh)[idx] = srcH[idx];
        ((uint4*)BFl)[idx] = srcL[idx];
    }
    __syncthreads();

    const float alpha = alpha_p[0];
    const float beta  = beta_p[0];

    // A-hi fragments hoisted (reused for all 4 s-chunks)
    uint4 ahv[4];
    #pragma unroll
    for (int ks = 0; ks < 4; ks++)
        ahv[ks] = ((const uint4*)AFh)[(wid * 4 + ks) * 32 + lane];

    float vb[2] = {-INFINITY, -INFINITY};
    int   sb[2] = {0, 0};

    #pragma unroll 1
    for (int cq = 0; cq < 4; cq++) {
        float4 acc[8];
        #pragma unroll
        for (int j = 0; j < 8; j++) acc[j] = make_float4(0.f, 0.f, 0.f, 0.f);

        #pragma unroll
        for (int ks = 0; ks < 4; ks++) {
            uint4 alv = ((const uint4*)AFl)[(wid * 4 + ks) * 32 + lane];
            // pass 1: hi * bh  — 8 independent accumulators back-to-back
            #pragma unroll
            for (int j = 0; j < 8; j++) {
                int nt = cq * 8 + j;
                uint2 bh = ((const uint2*)BFh)[(nt * 4 + ks) * 32 + lane];
                mma8(acc[j], (const uint32_t*)&ahv[ks], (const uint32_t*)&bh);
            }
            // pass 2: hi * bl
            #pragma unroll
            for (int j = 0; j < 8; j++) {
                int nt = cq * 8 + j;
                uint2 bl = ((const uint2*)BFl)[(nt * 4 + ks) * 32 + lane];
                mma8(acc[j], (const uint32_t*)&ahv[ks], (const uint32_t*)&bl);
            }
            // pass 3: lo * bh
            #pragma unroll
            for (int j = 0; j < 8; j++) {
                int nt = cq * 8 + j;
                uint2 bh = ((const uint2*)BFh)[(nt * 4 + ks) * 32 + lane];
                mma8(acc[j], (const uint32_t*)&alv, (const uint32_t*)&bh);
            }
        }

        // running affine argmax (ascending s, strict >)
        const int sbase = cq * 64;
        #pragma unroll
        for (int j = 0; j < 8; j++) {
            int s0 = sbase + j * 8 + 2 * tg;
            float v0 = fmaf(alpha, acc[j].x, beta);
            float v1 = fmaf(alpha, acc[j].y, beta);
            float v2 = fmaf(alpha, acc[j].z, beta);
            float v3 = fmaf(alpha, acc[j].w, beta);
            if (v0 > vb[0]) { vb[0] = v0; sb[0] = s0; }
            if (v1 > vb[0]) { vb[0] = v1; sb[0] = s0 + 1; }
            if (v2 > vb[1]) { vb[1] = v2; sb[1] = s0; }
            if (v3 > vb[1]) { vb[1] = v3; sb[1] = s0 + 1; }
        }
    }

    // reduce argmax across the 4 tg-lanes of each quad (rows g / g+8)
    #pragma unroll
    for (int r = 0; r < 2; r++) {
        #pragma unroll
        for (int off = 1; off < 4; off <<= 1) {
            float v2 = __shfl_xor_sync(0xffffffffu, vb[r], off);
            int   s2 = __shfl_xor_sync(0xffffffffu, sb[r], off);
            if (v2 > vb[r] || (v2 == vb[r] && s2 < sb[r])) { vb[r] = v2; sb[r] = s2; }
        }
    }
    if (tg == 0) {
        int row0 = wid * 16 + g;
        smv[row0]     = 1.f / (1.f + __expf(-vb[0]));
        sms[row0]     = sb[0];
        smv[row0 + 8] = 1.f / (1.f + __expf(-vb[1]));
        sms[row0 + 8] = sb[1];
    }
    __syncthreads();

    // gather + scale + write dispatched
    const float* cvm = &g_cv[(size_t)m * SS * SCn];
    #pragma unroll
    for (int it = 0; it < 16; it++) {
        int idx = tid + it * 256;
        int row = idx >> 5, k = idx & 31;
        float out = smv[row] * __ldg(&cvm[sms[row] * SCn + k]);
        g_disp[((size_t)(n * LL + l0 + row)) * HH + f * SCn + k] = out;
    }
}

// ---------------------------------------------------------------------------
extern "C" void kernel_launch(void* const* d_in, const int* in_sizes, int n_in,
                              void* d_out, int out_size)
{
    const float* x0      = (const float*)d_in[0];
    const float* center1 = (const float*)d_in[1];
    const float* W0      = (const float*)d_in[2];
    const float* b0      = (const float*)d_in[3];
    const float* W1      = (const float*)d_in[4];
    const float* b1      = (const float*)d_in[5];
    const float* Wm      = (const float*)d_in[6];
    const float* bm      = (const float*)d_in[7];
    const float* alpha   = (const float*)d_in[8];
    const float* beta    = (const float*)d_in[9];
    float* out           = (float*)d_out;

    float* c1p;   cudaGetSymbolAddress((void**)&c1p,  g_c1);
    float* x0pp;  cudaGetSymbolAddress((void**)&x0pp, g_x0p);
    float* dispp; cudaGetSymbolAddress((void**)&dispp, g_disp);

    const int simSmem  = (2 * 4096 + 2 * 8192) * 4 + 128 * 8;  // 99328
    const int mma3Smem = 4 * 4608 * 4;                          // 73728
    const int mma1Smem = 2 * 4608 * 4;                          // 36864
    cudaFuncSetAttribute(sim_mma, cudaFuncAttributeMaxDynamicSharedMemorySize, simSmem);
    cudaFuncSetAttribute(gemm_mma<3>, cudaFuncAttributeMaxDynamicSharedMemorySize, mma3Smem);
    cudaFuncSetAttribute(gemm_mma<1>, cudaFuncAttributeMaxDynamicSharedMemorySize, mma1Smem);

    // Fork a side stream so the center chain (K1 -> norm) overlaps K2.
    cudaStream_t s2;
    cudaStreamCreateWithFlags(&s2, cudaStreamNonBlocking);
    cudaEvent_t e0, e1;
    cudaEventCreateWithFlags(&e0, cudaEventDisableTiming);
    cudaEventCreateWithFlags(&e1, cudaEventDisableTiming);

    cudaEventRecord(e0, 0);
    cudaStreamWaitEvent(s2, e0, 0);

    // side stream: K1 (centers) + K1b (normalize/split)
    gemm_nt<64><<<dim3(1024 / 128, H2 / 64), 256, 0, s2>>>(center1, W1, b1, c1p, H2);
    center_norm_kernel<<<1024, 256, 0, s2>>>();
    cudaEventRecord(e1, s2);

    // main stream: K2 (x0 projection) runs concurrently with the center chain
    gemm_mma<3><<<dim3((NB * LL) / 128, HH / 128), 256, mma3Smem>>>(x0, W0, b0, x0pp, HH);

    // join: sim needs both x0p and the centers
    cudaStreamWaitEvent(0, e1, 0);

    // K3: sim (3xTF32 mma.sync) + argmax + sigmoid + gather -> dispatched
    sim_mma<<<dim3(LL / 128, MM), 256, simSmem>>>(alpha, beta);

    // K4: out = dispatched @ Wm^T + bm  (single-pass tf32, 128x128 tiles)
    gemm_mma<1><<<dim3((NB * LL) / 128, HH / 128), 256, mma1Smem>>>(dispp, Wm, bm, out, HH);
}

// round 15
// speedup vs baseline: 1.5821x; 1.0247x over previous
#include <cuda_runtime.h>
#include <math.h>
#include <stdint.h>

// Problem constants
#define NB   4
#define LL   4096
#define SS   256
#define HH   256
#define FCn  8
#define SCn  32
#define MM   32      // NB*FCn
#define H2   512
#define KK   256     // inner dim of dense GEMMs

typedef unsigned long long u64;

// Scratch (device globals; no dynamic allocation allowed)
__device__ float    g_c1[NB * SS * H2];       // center1 @ W1^T + b1
__device__ uint32_t g_cpFH[MM * 8192];        // tf32 hi of cpN, B-fragment layout
__device__ uint32_t g_cpFL[MM * 8192];        // tf32 lo residual, B-fragment layout
__device__ float    g_cv  [MM * SS * SCn];    // c_value
__device__ float    g_x0p [NB * LL * HH];     // x0 @ W0^T + b0
__device__ float    g_disp[NB * LL * HH];     // dispatched

// ---------------------------------------------------------------------------
// PTX helpers
// ---------------------------------------------------------------------------
__device__ __forceinline__ u64 ffma2(u64 a, u64 b, u64 c) {
    u64 d;
    asm("fma.rn.f32x2 %0, %1, %2, %3;" : "=l"(d) : "l"(a), "l"(b), "l"(c));
    return d;
}
__device__ __forceinline__ u64 pack2(float x, float y) {
    u64 r;
    asm("mov.b64 %0, {%1, %2};" : "=l"(r) : "f"(x), "f"(y));
    return r;
}
__device__ __forceinline__ float2 unpack2(u64 v) {
    float2 f;
    asm("mov.b64 {%0, %1}, %2;" : "=f"(f.x), "=f"(f.y) : "l"(v));
    return f;
}
__device__ __forceinline__ uint32_t f2tf32(float x) {
    uint32_t r;
    asm("cvt.rna.tf32.f32 %0, %1;" : "=r"(r) : "f"(x));
    return r;
}
// m16n8k8 tf32 warp MMA, D += A*B (fp32 accum)
__device__ __forceinline__ void mma8(float4& d, const uint32_t* a, const uint32_t* b) {
    asm("mma.sync.aligned.m16n8k8.row.col.f32.tf32.tf32.f32 "
        "{%0,%1,%2,%3}, {%4,%5,%6,%7}, {%8,%9}, {%0,%1,%2,%3};"
        : "+f"(d.x), "+f"(d.y), "+f"(d.z), "+f"(d.w)
        : "r"(a[0]), "r"(a[1]), "r"(a[2]), "r"(a[3]), "r"(b[0]), "r"(b[1]));
}

// Fragment-layout flat indices (units: uint32 words).
// A-frag: [rowtile(16 rows)][ks][lane][4 regs]
// B-frag: [ntile(8 cols)][ks][lane][2 regs]
__device__ __forceinline__ int afrag(int rowtile, int ks, int lane, int reg) {
    return ((rowtile * 4 + ks) * 32 + lane) * 4 + reg;
}
__device__ __forceinline__ int bfrag(int ntile, int ks, int lane, int reg) {
    return ((ntile * 4 + ks) * 32 + lane) * 2 + reg;
}

// ---------------------------------------------------------------------------
// Tensor-core GEMM via mma.sync tf32 (row-major stride-36 smem):
//   C[R][Hout] = A[R][256] @ B[Hout][256]^T + bias
// NPASS=1: plain tf32 — K4.  NPASS=3: hi/lo compensation (~fp32) — K2.
// Block tile 128x128, 8 warps: 4m x 2n; warp tile 32m x 64n. Pass-major.
// ---------------------------------------------------------------------------
template<int NPASS>
__global__ __launch_bounds__(256, 2) void gemm_mma(
    const float* __restrict__ A, const float* __restrict__ B,
    const float* __restrict__ bias, float* __restrict__ C, int Hout)
{
    extern __shared__ __align__(16) uint32_t msm[];
    uint32_t* Ah = msm;                                    // [128][36]
    uint32_t* Al = Ah + 4608;                              // NPASS==3 only
    uint32_t* Bh = (NPASS == 3) ? (Al + 4608) : (Ah + 4608);  // [128][36]
    uint32_t* Bl = Bh + 4608;                              // NPASS==3 only

    const int tid  = threadIdx.x;
    const int wid  = tid >> 5;
    const int lane = tid & 31;
    const int g  = lane >> 2;
    const int tg = lane & 3;
    const int mbase = (wid & 3) * 32;
    const int nbase = (wid >> 2) * 64;
    const int r0 = blockIdx.x * 128;
    const int h0 = blockIdx.y * 128;

    float4 acc[2][8];
    #pragma unroll
    for (int i = 0; i < 2; i++)
        #pragma unroll
        for (int j = 0; j < 8; j++) acc[i][j] = make_float4(0.f, 0.f, 0.f, 0.f);

    for (int c = 0; c < 8; c++) {
        __syncthreads();
        #pragma unroll
        for (int it = 0; it < 4; it++) {
            int idx = tid + it * 256;
            int row = idx >> 3, j = idx & 7;
            float4 v = *(const float4*)&A[(size_t)(r0 + row) * 256 + c * 32 + j * 4];
            uint32_t base = row * 36 + j * 4;
            float xs[4] = {v.x, v.y, v.z, v.w};
            #pragma unroll
            for (int t = 0; t < 4; t++) {
                uint32_t hi = f2tf32(xs[t]);
                Ah[base + t] = hi;
                if constexpr (NPASS == 3)
                    Al[base + t] = f2tf32(xs[t] - __uint_as_float(hi));
            }
        }
        #pragma unroll
        for (int it = 0; it < 4; it++) {
            int idx = tid + it * 256;
            int row = idx >> 3, j = idx & 7;
            float4 v = *(const float4*)&B[(size_t)(h0 + row) * 256 + c * 32 + j * 4];
            uint32_t base = row * 36 + j * 4;
            float xs[4] = {v.x, v.y, v.z, v.w};
            #pragma unroll
            for (int t = 0; t < 4; t++) {
                uint32_t hi = f2tf32(xs[t]);
                Bh[base + t] = hi;
                if constexpr (NPASS == 3)
                    Bl[base + t] = f2tf32(xs[t] - __uint_as_float(hi));
            }
        }
        __syncthreads();

        #pragma unroll
        for (int ks = 0; ks < 4; ks++) {
            const int k0 = ks * 8;
            uint32_t ah[2][4], al[2][4];
            #pragma unroll
            for (int i = 0; i < 2; i++) {
                uint32_t rb = (mbase + i * 16 + g) * 36 + k0 + tg;
                ah[i][0] = Ah[rb];
                ah[i][1] = Ah[rb + 8 * 36];
                ah[i][2] = Ah[rb + 4];
                ah[i][3] = Ah[rb + 8 * 36 + 4];
                if constexpr (NPASS == 3) {
                    al[i][0] = Al[rb];
                    al[i][1] = Al[rb + 8 * 36];
                    al[i][2] = Al[rb + 4];
                    al[i][3] = Al[rb + 8 * 36 + 4];
                }
            }
            // pass 1: hi * bh
            #pragma unroll
            for (int j = 0; j < 8; j++) {
                uint32_t rb = (nbase + j * 8 + g) * 36 + k0 + tg;
                uint32_t bh[2] = {Bh[rb], Bh[rb + 4]};
                mma8(acc[0][j], ah[0], bh);
                mma8(acc[1][j], ah[1], bh);
            }
            if constexpr (NPASS == 3) {
                // pass 2: hi * bl
                #pragma unroll
                for (int j = 0; j < 8; j++) {
                    uint32_t rb = (nbase + j * 8 + g) * 36 + k0 + tg;
                    uint32_t bl[2] = {Bl[rb], Bl[rb + 4]};
                    mma8(acc[0][j], ah[0], bl);
                    mma8(acc[1][j], ah[1], bl);
                }
                // pass 3: lo * bh
                #pragma unroll
                for (int j = 0; j < 8; j++) {
                    uint32_t rb = (nbase + j * 8 + g) * 36 + k0 + tg;
                    uint32_t bh[2] = {Bh[rb], Bh[rb + 4]};
                    mma8(acc[0][j], al[0], bh);
                    mma8(acc[1][j], al[1], bh);
                }
            }
        }
    }

    #pragma unroll
    for (int j = 0; j < 8; j++) {
        int col = h0 + nbase + j * 8 + 2 * tg;
        float2 bb = *(const float2*)&bias[col];
        #pragma unroll
        for (int i = 0; i < 2; i++) {
            int row = r0 + mbase + i * 16 + g;
            float2 o0 = make_float2(acc[i][j].x + bb.x, acc[i][j].y + bb.y);
            float2 o1 = make_float2(acc[i][j].z + bb.x, acc[i][j].w + bb.y);
            *(float2*)&C[(size_t)row * Hout + col] = o0;
            *(float2*)&C[(size_t)(row + 8) * Hout + col] = o1;
        }
    }
}

// ---------------------------------------------------------------------------
// Dense fp32 GEMM (K1 only)
// ---------------------------------------------------------------------------
template<int NT>
__global__ __launch_bounds__(256, 2) void gemm_nt(
    const float* __restrict__ A, const float* __restrict__ B,
    const float* __restrict__ bias, float* __restrict__ C, int Hout)
{
    constexpr int SN = NT / 16;
    __shared__ __align__(16) float as[32][132];
    __shared__ __align__(16) float bs[32][NT + 4];

    const int r0 = blockIdx.x * 128;
    const int h0 = blockIdx.y * NT;
    const int tid = threadIdx.x;
    const int tc = tid & 15;
    const int tr = tid >> 4;
    const int k4 = (tid & 7) * 4;
    const int rl = tid >> 3;

    u64 acc[4][SN];
    #pragma unroll
    for (int p = 0; p < 4; p++)
        #pragma unroll
        for (int j = 0; j < SN; j++) acc[p][j] = 0ull;

    for (int k0 = 0; k0 < KK; k0 += 32) {
        #pragma unroll
        for (int it = 0; it < 4; it++) {
            int row = rl + it * 32;
            float4 v = *(const float4*)&A[(size_t)(r0 + row) * KK + k0 + k4];
            as[k4 + 0][row] = v.x;
            as[k4 + 1][row] = v.y;
            as[k4 + 2][row] = v.z;
            as[k4 + 3][row] = v.w;
        }
        #pragma unroll
        for (int it = 0; it < NT / 32; it++) {
            int h = rl + it * 32;
            float4 v = *(const float4*)&B[(size_t)(h0 + h) * KK + k0 + k4];
            bs[k4 + 0][h] = v.x;
            bs[k4 + 1][h] = v.y;
            bs[k4 + 2][h] = v.z;
            bs[k4 + 3][h] = v.w;
        }
        __syncthreads();

        #pragma unroll 8
        for (int kk = 0; kk < 32; kk++) {
            ulonglong2 a01 = *(const ulonglong2*)&as[kk][tr * 8];
            ulonglong2 a23 = *(const ulonglong2*)&as[kk][tr * 8 + 4];
            u64 ap[4] = {a01.x, a01.y, a23.x, a23.y};
            #pragma unroll
            for (int jq = 0; jq < SN / 4; jq++) {
                float4 bv = *(const float4*)&bs[kk][tc * SN + jq * 4];
                u64 b0 = pack2(bv.x, bv.x);
                u64 b1 = pack2(bv.y, bv.y);
                u64 b2 = pack2(bv.z, bv.z);
                u64 b3 = pack2(bv.w, bv.w);
                #pragma unroll
                for (int p = 0; p < 4; p++) {
                    acc[p][jq * 4 + 0] = ffma2(ap[p], b0, acc[p][jq * 4 + 0]);
                    acc[p][jq * 4 + 1] = ffma2(ap[p], b1, acc[p][jq * 4 + 1]);
                    acc[p][jq * 4 + 2] = ffma2(ap[p], b2, acc[p][jq * 4 + 2]);
                    acc[p][jq * 4 + 3] = ffma2(ap[p], b3, acc[p][jq * 4 + 3]);
                }
            }
        }
        __syncthreads();
    }

    #pragma unroll
    for (int jq = 0; jq < SN / 4; jq++) {
        float4 bb = *(const float4*)&bias[h0 + tc * SN + jq * 4];
        #pragma unroll
        for (int p = 0; p < 4; p++) {
            float2 f0 = unpack2(acc[p][jq * 4 + 0]);
            float2 f1 = unpack2(acc[p][jq * 4 + 1]);
            float2 f2 = unpack2(acc[p][jq * 4 + 2]);
            float2 f3 = unpack2(acc[p][jq * 4 + 3]);
            int row0 = r0 + tr * 8 + 2 * p;
            float4 o0 = make_float4(f0.x + bb.x, f1.x + bb.y, f2.x + bb.z, f3.x + bb.w);
            float4 o1 = make_float4(f0.y + bb.x, f1.y + bb.y, f2.y + bb.z, f3.y + bb.w);
            *(float4*)&C[(size_t)row0 * Hout + h0 + tc * SN + jq * 4] = o0;
            *(float4*)&C[(size_t)(row0 + 1) * Hout + h0 + tc * SN + jq * 4] = o1;
        }
    }
}

// ---------------------------------------------------------------------------
// Split c1 -> c_point (l2-normalized, tf32 hi/lo in B-fragment layout) / c_value.
// ---------------------------------------------------------------------------
__global__ __launch_bounds__(256) void center_norm_kernel()
{
    int w    = (blockIdx.x * blockDim.x + threadIdx.x) >> 5;
    int lane = threadIdx.x & 31;
    int m = w >> 8;
    int s = w & 255;
    int n = m >> 3, f = m & 7;

    const float* row = &g_c1[((size_t)(n * SS + s)) * H2 + f * 64];
    float p = row[lane];
    float v = row[32 + lane];

    float sq = p * p;
    #pragma unroll
    for (int off = 16; off; off >>= 1)
        sq += __shfl_xor_sync(0xffffffffu, sq, off);

    float d = fmaxf(sqrtf(sq), 1e-12f);
    float pn = p / d;
    uint32_t hi = f2tf32(pn);
    uint32_t lo = f2tf32(pn - __uint_as_float(hi));

    int flat = bfrag(s >> 3, lane >> 3, (s & 7) * 4 + (lane & 3), (lane >> 2) & 1);
    g_cpFH[(size_t)m * 8192 + flat] = hi;
    g_cpFL[(size_t)m * 8192 + flat] = lo;
    g_cv[((size_t)(m * SS + s)) * SCn + lane] = v;
}

// ---------------------------------------------------------------------------
// Fused sim (3xTF32 mma.sync, pass-major) + argmax + sigmoid + gather.
// B HALF-resident (128 centers per half) -> smem 66.6KB -> 3 CTAs/SM.
// __launch_bounds__(256,3) caps regs at 85 for the extra CTA.
// block = (m, 128-l tile), 256 threads, 8 warps x 16 rows.
// ---------------------------------------------------------------------------
__global__ __launch_bounds__(256, 3) void sim_mma(
    const float* __restrict__ alpha_p, const float* __restrict__ beta_p)
{
    extern __shared__ __align__(16) uint32_t ssm[];
    uint32_t* AFh = ssm;                 // 8rt*4*32*4 = 4096 words
    uint32_t* AFl = AFh + 4096;
    uint32_t* BFh = AFl + 4096;          // 16nt*4*32*2 = 4096 words (half)
    uint32_t* BFl = BFh + 4096;
    float*    smv = (float*)(BFl + 4096);   // [128]
    int*      sms = (int*)(smv + 128);      // [128]

    const int m  = blockIdx.y;
    const int n  = m >> 3, f = m & 7;
    const int l0 = blockIdx.x * 128;
    const int tid  = threadIdx.x;
    const int wid  = tid >> 5;
    const int lane = tid & 31;
    const int g  = lane >> 2;
    const int tg = lane & 3;

    // A: load x0p rows, l2-normalize, tf32 hi/lo -> fragment layout
    #pragma unroll 4
    for (int i = 0; i < 16; i++) {
        int row = wid * 16 + i;
        float x = g_x0p[((size_t)(n * LL + l0 + row)) * HH + f * SCn + lane];
        float sq = x * x;
        #pragma unroll
        for (int off = 16; off; off >>= 1)
            sq += __shfl_xor_sync(0xffffffffu, sq, off);
        float xn = x / fmaxf(sqrtf(sq), 1e-12f);
        uint32_t hi = f2tf32(xn);
        int flat = afrag(wid, lane >> 3, (i & 7) * 4 + (lane & 3),
                         (i >> 3) + 2 * ((lane >> 2) & 1));
        AFh[flat] = hi;
        AFl[flat] = f2tf32(xn - __uint_as_float(hi));
    }

    const float alpha = alpha_p[0];
    const float beta  = beta_p[0];
    const uint4* srcH = (const uint4*)&g_cpFH[(size_t)m * 8192];
    const uint4* srcL = (const uint4*)&g_cpFL[(size_t)m * 8192];

    float vb[2] = {-INFINITY, -INFINITY};
    int   sb[2] = {0, 0};

    #pragma unroll 1
    for (int half = 0; half < 2; half++) {
        if (half) __syncthreads();   // all reads of previous B-half done
        // B: coalesced uint4 copy of this half's fragments (1024 uint4 each)
        #pragma unroll
        for (int it = 0; it < 4; it++) {
            int idx = tid + it * 256;
            ((uint4*)BFh)[idx] = srcH[half * 1024 + idx];
            ((uint4*)BFl)[idx] = srcL[half * 1024 + idx];
        }
        __syncthreads();             // covers A-prep on half 0

        #pragma unroll 1
        for (int cql = 0; cql < 2; cql++) {
            const int cq = half * 2 + cql;
            float4 acc[8];
            #pragma unroll
            for (int j = 0; j < 8; j++) acc[j] = make_float4(0.f, 0.f, 0.f, 0.f);

            #pragma unroll
            for (int ks = 0; ks < 4; ks++) {
                uint4 ahv = ((const uint4*)AFh)[(wid * 4 + ks) * 32 + lane];
                uint4 alv = ((const uint4*)AFl)[(wid * 4 + ks) * 32 + lane];
                // pass 1: hi * bh — independent accumulators back-to-back
                #pragma unroll
                for (int j = 0; j < 8; j++) {
                    int nt = cql * 8 + j;
                    uint2 bh = ((const uint2*)BFh)[(nt * 4 + ks) * 32 + lane];
                    mma8(acc[j], (const uint32_t*)&ahv, (const uint32_t*)&bh);
                }
                // pass 2: hi * bl
                #pragma unroll
                for (int j = 0; j < 8; j++) {
                    int nt = cql * 8 + j;
                    uint2 bl = ((const uint2*)BFl)[(nt * 4 + ks) * 32 + lane];
                    mma8(acc[j], (const uint32_t*)&ahv, (const uint32_t*)&bl);
                }
                // pass 3: lo * bh
                #pragma unroll
                for (int j = 0; j < 8; j++) {
                    int nt = cql * 8 + j;
                    uint2 bh = ((const uint2*)BFh)[(nt * 4 + ks) * 32 + lane];
                    mma8(acc[j], (const uint32_t*)&alv, (const uint32_t*)&bh);
                }
            }

            // running affine argmax (ascending s, strict >)
            const int sbase = cq * 64;
            #pragma unroll
            for (int j = 0; j < 8; j++) {
                int s0 = sbase + j * 8 + 2 * tg;
                float v0 = fmaf(alpha, acc[j].x, beta);
                float v1 = fmaf(alpha, acc[j].y, beta);
                float v2 = fmaf(alpha, acc[j].z, beta);
                float v3 = fmaf(alpha, acc[j].w, beta);
                if (v0 > vb[0]) { vb[0] = v0; sb[0] = s0; }
                if (v1 > vb[0]) { vb[0] = v1; sb[0] = s0 + 1; }
                if (v2 > vb[1]) { vb[1] = v2; sb[1] = s0; }
                if (v3 > vb[1]) { vb[1] = v3; sb[1] = s0 + 1; }
            }
        }
    }

    // reduce argmax across the 4 tg-lanes of each quad (rows g / g+8)
    #pragma unroll
    for (int r = 0; r < 2; r++) {
        #pragma unroll
        for (int off = 1; off < 4; off <<= 1) {
            float v2 = __shfl_xor_sync(0xffffffffu, vb[r], off);
            int   s2 = __shfl_xor_sync(0xffffffffu, sb[r], off);
            if (v2 > vb[r] || (v2 == vb[r] && s2 < sb[r])) { vb[r] = v2; sb[r] = s2; }
        }
    }
    if (tg == 0) {
        int row0 = wid * 16 + g;
        smv[row0]     = 1.f / (1.f + __expf(-vb[0]));
        sms[row0]     = sb[0];
        smv[row0 + 8] = 1.f / (1.f + __expf(-vb[1]));
        sms[row0 + 8] = sb[1];
    }
    __syncthreads();

    // gather + scale + write dispatched
    const float* cvm = &g_cv[(size_t)m * SS * SCn];
    #pragma unroll
    for (int it = 0; it < 16; it++) {
        int idx = tid + it * 256;
        int row = idx >> 5, k = idx & 31;
        float out = smv[row] * __ldg(&cvm[sms[row] * SCn + k]);
        g_disp[((size_t)(n * LL + l0 + row)) * HH + f * SCn + k] = out;
    }
}

// ---------------------------------------------------------------------------
extern "C" void kernel_launch(void* const* d_in, const int* in_sizes, int n_in,
                              void* d_out, int out_size)
{
    const float* x0      = (const float*)d_in[0];
    const float* center1 = (const float*)d_in[1];
    const float* W0      = (const float*)d_in[2];
    const float* b0      = (const float*)d_in[3];
    const float* W1      = (const float*)d_in[4];
    const float* b1      = (const float*)d_in[5];
    const float* Wm      = (const float*)d_in[6];
    const float* bm      = (const float*)d_in[7];
    const float* alpha   = (const float*)d_in[8];
    const float* beta    = (const float*)d_in[9];
    float* out           = (float*)d_out;

    float* c1p;   cudaGetSymbolAddress((void**)&c1p,  g_c1);
    float* x0pp;  cudaGetSymbolAddress((void**)&x0pp, g_x0p);
    float* dispp; cudaGetSymbolAddress((void**)&dispp, g_disp);

    const int simSmem  = (4 * 4096) * 4 + 128 * 8;              // 66560
    const int mma3Smem = 4 * 4608 * 4;                          // 73728
    const int mma1Smem = 2 * 4608 * 4;                          // 36864
    cudaFuncSetAttribute(sim_mma, cudaFuncAttributeMaxDynamicSharedMemorySize, simSmem);
    cudaFuncSetAttribute(gemm_mma<3>, cudaFuncAttributeMaxDynamicSharedMemorySize, mma3Smem);
    cudaFuncSetAttribute(gemm_mma<1>, cudaFuncAttributeMaxDynamicSharedMemorySize, mma1Smem);

    // Fork a side stream so the center chain (K1 -> norm) overlaps K2.
    cudaStream_t s2;
    cudaStreamCreateWithFlags(&s2, cudaStreamNonBlocking);
    cudaEvent_t e0, e1;
    cudaEventCreateWithFlags(&e0, cudaEventDisableTiming);
    cudaEventCreateWithFlags(&e1, cudaEventDisableTiming);

    cudaEventRecord(e0, 0);
    cudaStreamWaitEvent(s2, e0, 0);

    // side stream: K1 (centers) + K1b (normalize/split)
    gemm_nt<64><<<dim3(1024 / 128, H2 / 64), 256, 0, s2>>>(center1, W1, b1, c1p, H2);
    center_norm_kernel<<<1024, 256, 0, s2>>>();
    cudaEventRecord(e1, s2);

    // main stream: K2 (x0 projection) runs concurrently with the center chain
    gemm_mma<3><<<dim3((NB * LL) / 128, HH / 128), 256, mma3Smem>>>(x0, W0, b0, x0pp, HH);

    // join: sim needs both x0p and the centers
    cudaStreamWaitEvent(0, e1, 0);

    // K3: sim (3xTF32 mma.sync) + argmax + sigmoid + gather -> dispatched
    sim_mma<<<dim3(LL / 128, MM), 256, simSmem>>>(alpha, beta);

    // K4: out = dispatched @ Wm^T + bm  (single-pass tf32, 128x128 tiles)
    gemm_mma<1><<<dim3((NB * LL) / 128, HH / 128), 256, mma1Smem>>>(dispp, Wm, bm, out, HH);
}

// round 16
// speedup vs baseline: 1.6241x; 1.0265x over previous
#include <cuda_runtime.h>
#include <math.h>
#include <stdint.h>

// Problem constants
#define NB   4
#define LL   4096
#define SS   256
#define HH   256
#define FCn  8
#define SCn  32
#define MM   32      // NB*FCn
#define H2   512
#define KK   256     // inner dim of dense GEMMs

typedef unsigned long long u64;

// Scratch (device globals; no dynamic allocation allowed)
__device__ float    g_c1[NB * SS * H2];       // center1 @ W1^T + b1
__device__ uint32_t g_cpFH[MM * 8192];        // tf32 hi of cpN, B-fragment layout
__device__ uint32_t g_cpFL[MM * 8192];        // tf32 lo residual, B-fragment layout
__device__ float    g_cv  [MM * SS * SCn];    // c_value
__device__ float    g_x0p [NB * LL * HH];     // x0 @ W0^T + b0
__device__ float    g_disp[NB * LL * HH];     // dispatched

// ---------------------------------------------------------------------------
// PTX helpers
// ---------------------------------------------------------------------------
__device__ __forceinline__ u64 ffma2(u64 a, u64 b, u64 c) {
    u64 d;
    asm("fma.rn.f32x2 %0, %1, %2, %3;" : "=l"(d) : "l"(a), "l"(b), "l"(c));
    return d;
}
__device__ __forceinline__ u64 pack2(float x, float y) {
    u64 r;
    asm("mov.b64 %0, {%1, %2};" : "=l"(r) : "f"(x), "f"(y));
    return r;
}
__device__ __forceinline__ float2 unpack2(u64 v) {
    float2 f;
    asm("mov.b64 {%0, %1}, %2;" : "=f"(f.x), "=f"(f.y) : "l"(v));
    return f;
}
__device__ __forceinline__ uint32_t f2tf32(float x) {
    uint32_t r;
    asm("cvt.rna.tf32.f32 %0, %1;" : "=r"(r) : "f"(x));
    return r;
}
// m16n8k8 tf32 warp MMA, D += A*B (fp32 accum)
__device__ __forceinline__ void mma8(float4& d, const uint32_t* a, const uint32_t* b) {
    asm("mma.sync.aligned.m16n8k8.row.col.f32.tf32.tf32.f32 "
        "{%0,%1,%2,%3}, {%4,%5,%6,%7}, {%8,%9}, {%0,%1,%2,%3};"
        : "+f"(d.x), "+f"(d.y), "+f"(d.z), "+f"(d.w)
        : "r"(a[0]), "r"(a[1]), "r"(a[2]), "r"(a[3]), "r"(b[0]), "r"(b[1]));
}

// Fragment-layout flat indices (units: uint32 words).
// A-frag: [rowtile(16 rows)][ks][lane][4 regs]
// B-frag: [ntile(8 cols)][ks][lane][2 regs]
__device__ __forceinline__ int afrag(int rowtile, int ks, int lane, int reg) {
    return ((rowtile * 4 + ks) * 32 + lane) * 4 + reg;
}
__device__ __forceinline__ int bfrag(int ntile, int ks, int lane, int reg) {
    return ((ntile * 4 + ks) * 32 + lane) * 2 + reg;
}

// ---------------------------------------------------------------------------
// Tensor-core GEMM via mma.sync tf32 (row-major stride-36 smem):
//   C[R][Hout] = A[R][256] @ B[Hout][256]^T + bias
// NPASS=1: plain tf32 — K4.  NPASS=3: hi/lo compensation (~fp32) — K2.
// Block tile 128x128, 8 warps: 4m x 2n; warp tile 32m x 64n. Pass-major.
// ---------------------------------------------------------------------------
template<int NPASS>
__global__ __launch_bounds__(256, 2) void gemm_mma(
    const float* __restrict__ A, const float* __restrict__ B,
    const float* __restrict__ bias, float* __restrict__ C, int Hout)
{
    extern __shared__ __align__(16) uint32_t msm[];
    uint32_t* Ah = msm;                                    // [128][36]
    uint32_t* Al = Ah + 4608;                              // NPASS==3 only
    uint32_t* Bh = (NPASS == 3) ? (Al + 4608) : (Ah + 4608);  // [128][36]
    uint32_t* Bl = Bh + 4608;                              // NPASS==3 only

    const int tid  = threadIdx.x;
    const int wid  = tid >> 5;
    const int lane = tid & 31;
    const int g  = lane >> 2;
    const int tg = lane & 3;
    const int mbase = (wid & 3) * 32;
    const int nbase = (wid >> 2) * 64;
    const int r0 = blockIdx.x * 128;
    const int h0 = blockIdx.y * 128;

    float4 acc[2][8];
    #pragma unroll
    for (int i = 0; i < 2; i++)
        #pragma unroll
        for (int j = 0; j < 8; j++) acc[i][j] = make_float4(0.f, 0.f, 0.f, 0.f);

    for (int c = 0; c < 8; c++) {
        __syncthreads();
        #pragma unroll
        for (int it = 0; it < 4; it++) {
            int idx = tid + it * 256;
            int row = idx >> 3, j = idx & 7;
            float4 v = *(const float4*)&A[(size_t)(r0 + row) * 256 + c * 32 + j * 4];
            uint32_t base = row * 36 + j * 4;
            float xs[4] = {v.x, v.y, v.z, v.w};
            #pragma unroll
            for (int t = 0; t < 4; t++) {
                uint32_t hi = f2tf32(xs[t]);
                Ah[base + t] = hi;
                if constexpr (NPASS == 3)
                    Al[base + t] = f2tf32(xs[t] - __uint_as_float(hi));
            }
        }
        #pragma unroll
        for (int it = 0; it < 4; it++) {
            int idx = tid + it * 256;
            int row = idx >> 3, j = idx & 7;
            float4 v = *(const float4*)&B[(size_t)(h0 + row) * 256 + c * 32 + j * 4];
            uint32_t base = row * 36 + j * 4;
            float xs[4] = {v.x, v.y, v.z, v.w};
            #pragma unroll
            for (int t = 0; t < 4; t++) {
                uint32_t hi = f2tf32(xs[t]);
                Bh[base + t] = hi;
                if constexpr (NPASS == 3)
                    Bl[base + t] = f2tf32(xs[t] - __uint_as_float(hi));
            }
        }
        __syncthreads();

        #pragma unroll
        for (int ks = 0; ks < 4; ks++) {
            const int k0 = ks * 8;
            uint32_t ah[2][4], al[2][4];
            #pragma unroll
            for (int i = 0; i < 2; i++) {
                uint32_t rb = (mbase + i * 16 + g) * 36 + k0 + tg;
                ah[i][0] = Ah[rb];
                ah[i][1] = Ah[rb + 8 * 36];
                ah[i][2] = Ah[rb + 4];
                ah[i][3] = Ah[rb + 8 * 36 + 4];
                if constexpr (NPASS == 3) {
                    al[i][0] = Al[rb];
                    al[i][1] = Al[rb + 8 * 36];
                    al[i][2] = Al[rb + 4];
                    al[i][3] = Al[rb + 8 * 36 + 4];
                }
            }
            // pass 1: hi * bh
            #pragma unroll
            for (int j = 0; j < 8; j++) {
                uint32_t rb = (nbase + j * 8 + g) * 36 + k0 + tg;
                uint32_t bh[2] = {Bh[rb], Bh[rb + 4]};
                mma8(acc[0][j], ah[0], bh);
                mma8(acc[1][j], ah[1], bh);
            }
            if constexpr (NPASS == 3) {
                // pass 2: hi * bl
                #pragma unroll
                for (int j = 0; j < 8; j++) {
                    uint32_t rb = (nbase + j * 8 + g) * 36 + k0 + tg;
                    uint32_t bl[2] = {Bl[rb], Bl[rb + 4]};
                    mma8(acc[0][j], ah[0], bl);
                    mma8(acc[1][j], ah[1], bl);
                }
                // pass 3: lo * bh
                #pragma unroll
                for (int j = 0; j < 8; j++) {
                    uint32_t rb = (nbase + j * 8 + g) * 36 + k0 + tg;
                    uint32_t bh[2] = {Bh[rb], Bh[rb + 4]};
                    mma8(acc[0][j], al[0], bh);
                    mma8(acc[1][j], al[1], bh);
                }
            }
        }
    }

    #pragma unroll
    for (int j = 0; j < 8; j++) {
        int col = h0 + nbase + j * 8 + 2 * tg;
        float2 bb = *(const float2*)&bias[col];
        #pragma unroll
        for (int i = 0; i < 2; i++) {
            int row = r0 + mbase + i * 16 + g;
            float2 o0 = make_float2(acc[i][j].x + bb.x, acc[i][j].y + bb.y);
            float2 o1 = make_float2(acc[i][j].z + bb.x, acc[i][j].w + bb.y);
            *(float2*)&C[(size_t)row * Hout + col] = o0;
            *(float2*)&C[(size_t)(row + 8) * Hout + col] = o1;
        }
    }
}

// ---------------------------------------------------------------------------
// Dense fp32 GEMM (K1 only)
// ---------------------------------------------------------------------------
template<int NT>
__global__ __launch_bounds__(256, 2) void gemm_nt(
    const float* __restrict__ A, const float* __restrict__ B,
    const float* __restrict__ bias, float* __restrict__ C, int Hout)
{
    constexpr int SN = NT / 16;
    __shared__ __align__(16) float as[32][132];
    __shared__ __align__(16) float bs[32][NT + 4];

    const int r0 = blockIdx.x * 128;
    const int h0 = blockIdx.y * NT;
    const int tid = threadIdx.x;
    const int tc = tid & 15;
    const int tr = tid >> 4;
    const int k4 = (tid & 7) * 4;
    const int rl = tid >> 3;

    u64 acc[4][SN];
    #pragma unroll
    for (int p = 0; p < 4; p++)
        #pragma unroll
        for (int j = 0; j < SN; j++) acc[p][j] = 0ull;

    for (int k0 = 0; k0 < KK; k0 += 32) {
        #pragma unroll
        for (int it = 0; it < 4; it++) {
            int row = rl + it * 32;
            float4 v = *(const float4*)&A[(size_t)(r0 + row) * KK + k0 + k4];
            as[k4 + 0][row] = v.x;
            as[k4 + 1][row] = v.y;
            as[k4 + 2][row] = v.z;
            as[k4 + 3][row] = v.w;
        }
        #pragma unroll
        for (int it = 0; it < NT / 32; it++) {
            int h = rl + it * 32;
            float4 v = *(const float4*)&B[(size_t)(h0 + h) * KK + k0 + k4];
            bs[k4 + 0][h] = v.x;
            bs[k4 + 1][h] = v.y;
            bs[k4 + 2][h] = v.z;
            bs[k4 + 3][h] = v.w;
        }
        __syncthreads();

        #pragma unroll 8
        for (int kk = 0; kk < 32; kk++) {
            ulonglong2 a01 = *(const ulonglong2*)&as[kk][tr * 8];
            ulonglong2 a23 = *(const ulonglong2*)&as[kk][tr * 8 + 4];
            u64 ap[4] = {a01.x, a01.y, a23.x, a23.y};
            #pragma unroll
            for (int jq = 0; jq < SN / 4; jq++) {
                float4 bv = *(const float4*)&bs[kk][tc * SN + jq * 4];
                u64 b0 = pack2(bv.x, bv.x);
                u64 b1 = pack2(bv.y, bv.y);
                u64 b2 = pack2(bv.z, bv.z);
                u64 b3 = pack2(bv.w, bv.w);
                #pragma unroll
                for (int p = 0; p < 4; p++) {
                    acc[p][jq * 4 + 0] = ffma2(ap[p], b0, acc[p][jq * 4 + 0]);
                    acc[p][jq * 4 + 1] = ffma2(ap[p], b1, acc[p][jq * 4 + 1]);
                    acc[p][jq * 4 + 2] = ffma2(ap[p], b2, acc[p][jq * 4 + 2]);
                    acc[p][jq * 4 + 3] = ffma2(ap[p], b3, acc[p][jq * 4 + 3]);
                }
            }
        }
        __syncthreads();
    }

    #pragma unroll
    for (int jq = 0; jq < SN / 4; jq++) {
        float4 bb = *(const float4*)&bias[h0 + tc * SN + jq * 4];
        #pragma unroll
        for (int p = 0; p < 4; p++) {
            float2 f0 = unpack2(acc[p][jq * 4 + 0]);
            float2 f1 = unpack2(acc[p][jq * 4 + 1]);
            float2 f2 = unpack2(acc[p][jq * 4 + 2]);
            float2 f3 = unpack2(acc[p][jq * 4 + 3]);
            int row0 = r0 + tr * 8 + 2 * p;
            float4 o0 = make_float4(f0.x + bb.x, f1.x + bb.y, f2.x + bb.z, f3.x + bb.w);
            float4 o1 = make_float4(f0.y + bb.x, f1.y + bb.y, f2.y + bb.z, f3.y + bb.w);
            *(float4*)&C[(size_t)row0 * Hout + h0 + tc * SN + jq * 4] = o0;
            *(float4*)&C[(size_t)(row0 + 1) * Hout + h0 + tc * SN + jq * 4] = o1;
        }
    }
}

// ---------------------------------------------------------------------------
// Split c1 -> c_point (l2-normalized, tf32 hi/lo in B-fragment layout) / c_value.
// ---------------------------------------------------------------------------
__global__ __launch_bounds__(256) void center_norm_kernel()
{
    int w    = (blockIdx.x * blockDim.x + threadIdx.x) >> 5;
    int lane = threadIdx.x & 31;
    int m = w >> 8;
    int s = w & 255;
    int n = m >> 3, f = m & 7;

    const float* row = &g_c1[((size_t)(n * SS + s)) * H2 + f * 64];
    float p = row[lane];
    float v = row[32 + lane];

    float sq = p * p;
    #pragma unroll
    for (int off = 16; off; off >>= 1)
        sq += __shfl_xor_sync(0xffffffffu, sq, off);

    float d = fmaxf(sqrtf(sq), 1e-12f);
    float pn = p / d;
    uint32_t hi = f2tf32(pn);
    uint32_t lo = f2tf32(pn - __uint_as_float(hi));

    int flat = bfrag(s >> 3, lane >> 3, (s & 7) * 4 + (lane & 3), (lane >> 2) & 1);
    g_cpFH[(size_t)m * 8192 + flat] = hi;
    g_cpFL[(size_t)m * 8192 + flat] = lo;
    g_cv[((size_t)(m * SS + s)) * SCn + lane] = v;
}

// ---------------------------------------------------------------------------
// Fused sim (3xTF32 mma.sync, pass-major) + argmax + sigmoid + gather.
// B QUARTER-resident (64 centers/chunk) -> smem 50.2KB, regs<=64 -> 4 CTAs/SM.
// A fragments loaded per-ks from smem (no register hoist) to fit 64 regs.
// block = (m, 128-l tile), 256 threads, 8 warps x 16 rows.
// ---------------------------------------------------------------------------
__global__ __launch_bounds__(256, 4) void sim_mma(
    const float* __restrict__ alpha_p, const float* __restrict__ beta_p)
{
    extern __shared__ __align__(16) uint32_t ssm[];
    uint32_t* AFh = ssm;                 // 8rt*4*32*4 = 4096 words
    uint32_t* AFl = AFh + 4096;
    uint32_t* BFh = AFl + 4096;          // 8nt*4*32*2 = 2048 words (quarter)
    uint32_t* BFl = BFh + 2048;
    float*    smv = (float*)(BFl + 2048);   // [128]
    int*      sms = (int*)(smv + 128);      // [128]

    const int m  = blockIdx.y;
    const int n  = m >> 3, f = m & 7;
    const int l0 = blockIdx.x * 128;
    const int tid  = threadIdx.x;
    const int wid  = tid >> 5;
    const int lane = tid & 31;
    const int g  = lane >> 2;
    const int tg = lane & 3;

    // A: load x0p rows, l2-normalize, tf32 hi/lo -> fragment layout
    #pragma unroll 4
    for (int i = 0; i < 16; i++) {
        int row = wid * 16 + i;
        float x = g_x0p[((size_t)(n * LL + l0 + row)) * HH + f * SCn + lane];
        float sq = x * x;
        #pragma unroll
        for (int off = 16; off; off >>= 1)
            sq += __shfl_xor_sync(0xffffffffu, sq, off);
        float xn = x / fmaxf(sqrtf(sq), 1e-12f);
        uint32_t hi = f2tf32(xn);
        int flat = afrag(wid, lane >> 3, (i & 7) * 4 + (lane & 3),
                         (i >> 3) + 2 * ((lane >> 2) & 1));
        AFh[flat] = hi;
        AFl[flat] = f2tf32(xn - __uint_as_float(hi));
    }

    const float alpha = alpha_p[0];
    const float beta  = beta_p[0];
    const uint4* srcH = (const uint4*)&g_cpFH[(size_t)m * 8192];
    const uint4* srcL = (const uint4*)&g_cpFL[(size_t)m * 8192];

    float vb[2] = {-INFINITY, -INFINITY};
    int   sb[2] = {0, 0};

    #pragma unroll 1
    for (int qt = 0; qt < 4; qt++) {
        if (qt) __syncthreads();     // all reads of previous B-quarter done
        // B: coalesced uint4 copy of this quarter's fragments (512 uint4 each)
        #pragma unroll
        for (int it = 0; it < 2; it++) {
            int idx = tid + it * 256;
            ((uint4*)BFh)[idx] = srcH[qt * 512 + idx];
            ((uint4*)BFl)[idx] = srcL[qt * 512 + idx];
        }
        __syncthreads();             // covers A-prep on qt 0

        float4 acc[8];
        #pragma unroll
        for (int j = 0; j < 8; j++) acc[j] = make_float4(0.f, 0.f, 0.f, 0.f);

        #pragma unroll
        for (int ks = 0; ks < 4; ks++) {
            uint4 ahv = ((const uint4*)AFh)[(wid * 4 + ks) * 32 + lane];
            uint4 alv = ((const uint4*)AFl)[(wid * 4 + ks) * 32 + lane];
            // pass 1: hi * bh — independent accumulators back-to-back
            #pragma unroll
            for (int j = 0; j < 8; j++) {
                uint2 bh = ((const uint2*)BFh)[(j * 4 + ks) * 32 + lane];
                mma8(acc[j], (const uint32_t*)&ahv, (const uint32_t*)&bh);
            }
            // pass 2: hi * bl
            #pragma unroll
            for (int j = 0; j < 8; j++) {
                uint2 bl = ((const uint2*)BFl)[(j * 4 + ks) * 32 + lane];
                mma8(acc[j], (const uint32_t*)&ahv, (const uint32_t*)&bl);
            }
            // pass 3: lo * bh
            #pragma unroll
            for (int j = 0; j < 8; j++) {
                uint2 bh = ((const uint2*)BFh)[(j * 4 + ks) * 32 + lane];
                mma8(acc[j], (const uint32_t*)&alv, (const uint32_t*)&bh);
            }
        }

        // running affine argmax (ascending s, strict >)
        const int sbase = qt * 64;
        #pragma unroll
        for (int j = 0; j < 8; j++) {
            int s0 = sbase + j * 8 + 2 * tg;
            float v0 = fmaf(alpha, acc[j].x, beta);
            float v1 = fmaf(alpha, acc[j].y, beta);
            float v2 = fmaf(alpha, acc[j].z, beta);
            float v3 = fmaf(alpha, acc[j].w, beta);
            if (v0 > vb[0]) { vb[0] = v0; sb[0] = s0; }
            if (v1 > vb[0]) { vb[0] = v1; sb[0] = s0 + 1; }
            if (v2 > vb[1]) { vb[1] = v2; sb[1] = s0; }
            if (v3 > vb[1]) { vb[1] = v3; sb[1] = s0 + 1; }
        }
    }

    // reduce argmax across the 4 tg-lanes of each quad (rows g / g+8)
    #pragma unroll
    for (int r = 0; r < 2; r++) {
        #pragma unroll
        for (int off = 1; off < 4; off <<= 1) {
            float v2 = __shfl_xor_sync(0xffffffffu, vb[r], off);
            int   s2 = __shfl_xor_sync(0xffffffffu, sb[r], off);
            if (v2 > vb[r] || (v2 == vb[r] && s2 < sb[r])) { vb[r] = v2; sb[r] = s2; }
        }
    }
    if (tg == 0) {
        int row0 = wid * 16 + g;
        smv[row0]     = 1.f / (1.f + __expf(-vb[0]));
        sms[row0]     = sb[0];
        smv[row0 + 8] = 1.f / (1.f + __expf(-vb[1]));
        sms[row0 + 8] = sb[1];
    }
    __syncthreads();

    // gather + scale + write dispatched
    const float* cvm = &g_cv[(size_t)m * SS * SCn];
    #pragma unroll
    for (int it = 0; it < 16; it++) {
        int idx = tid + it * 256;
        int row = idx >> 5, k = idx & 31;
        float out = smv[row] * __ldg(&cvm[sms[row] * SCn + k]);
        g_disp[((size_t)(n * LL + l0 + row)) * HH + f * SCn + k] = out;
    }
}

// ---------------------------------------------------------------------------
extern "C" void kernel_launch(void* const* d_in, const int* in_sizes, int n_in,
                              void* d_out, int out_size)
{
    const float* x0      = (const float*)d_in[0];
    const float* center1 = (const float*)d_in[1];
    const float* W0      = (const float*)d_in[2];
    const float* b0      = (const float*)d_in[3];
    const float* W1      = (const float*)d_in[4];
    const float* b1      = (const float*)d_in[5];
    const float* Wm      = (const float*)d_in[6];
    const float* bm      = (const float*)d_in[7];
    const float* alpha   = (const float*)d_in[8];
    const float* beta    = (const float*)d_in[9];
    float* out           = (float*)d_out;

    float* c1p;   cudaGetSymbolAddress((void**)&c1p,  g_c1);
    float* x0pp;  cudaGetSymbolAddress((void**)&x0pp, g_x0p);
    float* dispp; cudaGetSymbolAddress((void**)&dispp, g_disp);

    const int simSmem  = (2 * 4096 + 2 * 2048) * 4 + 128 * 8;   // 50176
    const int mma3Smem = 4 * 4608 * 4;                          // 73728
    const int mma1Smem = 2 * 4608 * 4;                          // 36864
    cudaFuncSetAttribute(sim_mma, cudaFuncAttributeMaxDynamicSharedMemorySize, simSmem);
    cudaFuncSetAttribute(gemm_mma<3>, cudaFuncAttributeMaxDynamicSharedMemorySize, mma3Smem);
    cudaFuncSetAttribute(gemm_mma<1>, cudaFuncAttributeMaxDynamicSharedMemorySize, mma1Smem);

    // Fork a side stream so the center chain (K1 -> norm) overlaps K2.
    cudaStream_t s2;
    cudaStreamCreateWithFlags(&s2, cudaStreamNonBlocking);
    cudaEvent_t e0, e1;
    cudaEventCreateWithFlags(&e0, cudaEventDisableTiming);
    cudaEventCreateWithFlags(&e1, cudaEventDisableTiming);

    cudaEventRecord(e0, 0);
    cudaStreamWaitEvent(s2, e0, 0);

    // side stream: K1 (centers) + K1b (normalize/split)
    gemm_nt<64><<<dim3(1024 / 128, H2 / 64), 256, 0, s2>>>(center1, W1, b1, c1p, H2);
    center_norm_kernel<<<1024, 256, 0, s2>>>();
    cudaEventRecord(e1, s2);

    // main stream: K2 (x0 projection) runs concurrently with the center chain
    gemm_mma<3><<<dim3((NB * LL) / 128, HH / 128), 256, mma3Smem>>>(x0, W0, b0, x0pp, HH);

    // join: sim needs both x0p and the centers
    cudaStreamWaitEvent(0, e1, 0);

    // K3: sim (3xTF32 mma.sync) + argmax + sigmoid + gather -> dispatched
    sim_mma<<<dim3(LL / 128, MM), 256, simSmem>>>(alpha, beta);

    // K4: out = dispatched @ Wm^T + bm  (single-pass tf32, 128x128 tiles)
    gemm_mma<1><<<dim3((NB * LL) / 128, HH / 128), 256, mma1Smem>>>(dispp, Wm, bm, out, HH);
}